// round 7
// baseline (speedup 1.0000x reference)
#include <cuda_runtime.h>
#include <cstdint>

#define NB 2
#define NS 2048
#define ND 1024
#define NH 16
#define NHD 64

// Scratch: projected Q (pre-scaled by 0.125*log2e) and K, plus 1/(16*rowsum).
__device__ float g_Q[NB * NH * NS * NHD];     // [bh, s, hd]
__device__ float g_K[NB * NH * NS * NHD];     // [bh, s, hd]
__device__ float g_Linv[NB * NH * NS];        // [bh, q]

// ---------------------------------------------------------------------------
__device__ __forceinline__ uint32_t smem_u32(const void* p) {
    uint32_t a;
    asm("{ .reg .u64 t; cvta.to.shared.u64 t, %1; cvt.u32.u64 %0, t; }"
        : "=r"(a) : "l"(p));
    return a;
}
__device__ __forceinline__ void cp16(uint32_t s, const void* g) {
    asm volatile("cp.async.cg.shared.global [%0], [%1], 16;" :: "r"(s), "l"(g));
}
#define CP_COMMIT() asm volatile("cp.async.commit_group;" ::: "memory")
#define CP_WAIT1()  asm volatile("cp.async.wait_group 1;" ::: "memory")

__device__ __forceinline__ float ex2a(float x) {
    float y;
    asm("ex2.approx.f32 %0, %1;" : "=f"(y) : "f"(x));
    return y;
}

#define MMA_TF32(d, a, b0, b1)                                                 \
    asm volatile(                                                              \
        "mma.sync.aligned.m16n8k8.row.col.f32.tf32.tf32.f32 "                  \
        "{%0,%1,%2,%3}, {%4,%5,%6,%7}, {%8,%9}, {%0,%1,%2,%3};"                \
        : "+f"((d)[0]), "+f"((d)[1]), "+f"((d)[2]), "+f"((d)[3])               \
        : "r"((a)[0]), "r"((a)[1]), "r"((a)[2]), "r"((a)[3]),                  \
          "r"(b0), "r"(b1))

// Q scale folds 1/sqrt(64) and log2(e) so softmax uses raw 2^x.
#define QSCALE 0.18033688011112042f

// ---------------------------------------------------------------------------
// Projection GEMM (R5-proven tiling): Out[b,h,s,hd] = (X @ W^T + bias)*scale
//   BM=128, BN=128, BK=32, double-buffered cp.async. 8 warps, warp = 16x128.
//   acc = 64 regs/thread -> no spills.
// ---------------------------------------------------------------------------
#define PJ_STRIDE 36
#define PJ_BUF (128 * PJ_STRIDE)
#define PJ_SMEM_TOTAL (4 * PJ_BUF * 4)                 // 73,728 B

__global__ __launch_bounds__(256) void proj_mma_kernel(
    const float* __restrict__ X, const float* __restrict__ W,
    const float* __restrict__ bias, float scale, int which)
{
    float* __restrict__ Out = which ? g_K : g_Q;
    extern __shared__ float pjs[];
    float* Xs = pjs;                  // [2][128][36]
    float* Ws = pjs + 2 * PJ_BUF;     // [2][128][36]
    const uint32_t sb_x = smem_u32(Xs);
    const uint32_t sb_w = smem_u32(Ws);

    const int tid = threadIdx.x;
    const int lane = tid & 31, wid = tid >> 5;
    const int lq = lane & 3, lg = lane >> 2;
    const int n0 = blockIdx.x * 128, m0 = blockIdx.y * 128;
    const int row_lo = wid * 16 + lg;

    const int ld_row = tid >> 1;
    const int ld_c0 = (tid & 1) * 16;
    auto prefetch = [&](int st, int kb) {
        uint32_t xs = sb_x + (uint32_t)((st * PJ_BUF + ld_row * PJ_STRIDE + ld_c0) * 4);
        uint32_t ws = sb_w + (uint32_t)((st * PJ_BUF + ld_row * PJ_STRIDE + ld_c0) * 4);
        const float* xg = X + (size_t)(m0 + ld_row) * ND + kb + ld_c0;
        const float* wg = W + (size_t)(n0 + ld_row) * ND + kb + ld_c0;
#pragma unroll
        for (int i = 0; i < 4; i++) {
            cp16(xs + i * 16, xg + i * 4);
            cp16(ws + i * 16, wg + i * 4);
        }
    };

    float acc[16][4];
#pragma unroll
    for (int nt = 0; nt < 16; nt++)
#pragma unroll
        for (int j = 0; j < 4; j++) acc[nt][j] = 0.0f;

    prefetch(0, 0);
    CP_COMMIT();

    for (int kb_i = 0; kb_i < ND / 32; kb_i++) {
        if (kb_i + 1 < ND / 32) prefetch((kb_i + 1) & 1, (kb_i + 1) * 32);
        CP_COMMIT();
        CP_WAIT1();
        __syncthreads();

        const float* Xb = Xs + (kb_i & 1) * PJ_BUF;
        const float* Wb = Ws + (kb_i & 1) * PJ_BUF;
#pragma unroll
        for (int s = 0; s < 4; s++) {
            uint32_t a[4];
            a[0] = __float_as_uint(Xb[row_lo * PJ_STRIDE + s * 8 + lq]);
            a[1] = __float_as_uint(Xb[(row_lo + 8) * PJ_STRIDE + s * 8 + lq]);
            a[2] = __float_as_uint(Xb[row_lo * PJ_STRIDE + s * 8 + lq + 4]);
            a[3] = __float_as_uint(Xb[(row_lo + 8) * PJ_STRIDE + s * 8 + lq + 4]);
#pragma unroll
            for (int nt = 0; nt < 16; nt++) {
                uint32_t b0 = __float_as_uint(Wb[(nt * 8 + lg) * PJ_STRIDE + s * 8 + lq]);
                uint32_t b1 = __float_as_uint(Wb[(nt * 8 + lg) * PJ_STRIDE + s * 8 + lq + 4]);
                MMA_TF32(acc[nt], a, b0, b1);
            }
        }
        __syncthreads();
    }

    // Epilogue: bias + scale, scatter to [bh, s, hd]
    const int m_lo = m0 + row_lo;
    const int b_lo = m_lo >> 11, s_lo = m_lo & 2047;
    const int m_hi = m_lo + 8;
    const int b_hi = m_hi >> 11, s_hi = m_hi & 2047;
#pragma unroll
    for (int nt = 0; nt < 16; nt++) {
        int n = n0 + nt * 8 + 2 * lq;
        float2 bb = *(const float2*)&bias[n];
        int h = n >> 6, hd = n & 63;
        float2 o0, o1;
        o0.x = (acc[nt][0] + bb.x) * scale;
        o0.y = (acc[nt][1] + bb.y) * scale;
        o1.x = (acc[nt][2] + bb.x) * scale;
        o1.y = (acc[nt][3] + bb.y) * scale;
        *(float2*)&Out[((size_t)(b_lo * NH + h) * NS + s_lo) * NHD + hd] = o0;
        *(float2*)&Out[((size_t)(b_hi * NH + h) * NS + s_hi) * NHD + hd] = o1;
    }
}

// ---------------------------------------------------------------------------
// Pass 1: rowsums of 2^scores -> g_Linv = 1/(16*rowsum).
//   CTA = (bh, q-tile 128), loops 16 k-tiles of 128. 8 warps, warp = 16x128.
//   acc 64 regs; each warp owns complete rows -> direct Linv write.
// ---------------------------------------------------------------------------
#define P1_STRIDE 68
#define P1_KOFF (128 * P1_STRIDE * 4)                  // 34,816
#define P1_SMEM_TOTAL (P1_KOFF + 2 * 128 * P1_STRIDE * 4)  // 104,448 B

__global__ __launch_bounds__(256) void pass1_kernel()
{
    extern __shared__ char smem[];
    float* Qs = (float*)smem;                    // [128][68]
    float* Ks = (float*)(smem + P1_KOFF);        // [2][128][68]
    const uint32_t sb_q = smem_u32(Qs);
    const uint32_t sb_k = smem_u32(Ks);

    const int tid = threadIdx.x;
    const int lane = tid & 31, wid = tid >> 5;
    const int lq = lane & 3, lg = lane >> 2;
    const int bh = blockIdx.x;
    const int q0 = blockIdx.y * 128;

    const int r_ld = tid >> 1, c_ld = (tid & 1) * 32;
    auto prefetchK = [&](int st, int kt) {
        uint32_t ks = sb_k + (uint32_t)((st * 128 * P1_STRIDE + r_ld * P1_STRIDE + c_ld) * 4);
        const float* kg = g_K + ((size_t)bh * NS + kt * 128 + r_ld) * NHD + c_ld;
#pragma unroll
        for (int i = 0; i < 8; i++) cp16(ks + i * 16, kg + i * 4);
    };

    // Stage Q tile (raw fp32; HMMA truncates — matches pass2 bitwise)
    {
        uint32_t qs = sb_q + (uint32_t)((r_ld * P1_STRIDE + c_ld) * 4);
        const float* qg = g_Q + ((size_t)bh * NS + q0 + r_ld) * NHD + c_ld;
#pragma unroll
        for (int i = 0; i < 8; i++) cp16(qs + i * 16, qg + i * 4);
    }
    prefetchK(0, 0);
    CP_COMMIT();
    asm volatile("cp.async.wait_group 0;" ::: "memory");
    __syncthreads();

    const int row_lo = wid * 16 + lg;
    uint32_t afr[8][4];
#pragma unroll
    for (int s = 0; s < 8; s++) {
        afr[s][0] = __float_as_uint(Qs[row_lo * P1_STRIDE + s * 8 + lq]);
        afr[s][1] = __float_as_uint(Qs[(row_lo + 8) * P1_STRIDE + s * 8 + lq]);
        afr[s][2] = __float_as_uint(Qs[row_lo * P1_STRIDE + s * 8 + lq + 4]);
        afr[s][3] = __float_as_uint(Qs[(row_lo + 8) * P1_STRIDE + s * 8 + lq + 4]);
    }

    float rs0 = 0.0f, rs1 = 0.0f;

    for (int kt = 0; kt < NS / 128; kt++) {
        if (kt + 1 < NS / 128) prefetchK((kt + 1) & 1, kt + 1);
        CP_COMMIT();
        CP_WAIT1();
        __syncthreads();

        const float* Kb = Ks + (kt & 1) * 128 * P1_STRIDE;

        float acc[16][4];
#pragma unroll
        for (int nt = 0; nt < 16; nt++)
#pragma unroll
            for (int j = 0; j < 4; j++) acc[nt][j] = 0.0f;

#pragma unroll
        for (int s = 0; s < 8; s++) {
#pragma unroll
            for (int nt = 0; nt < 16; nt++) {
                const int col = nt * 8 + lg;
                uint32_t b0 = __float_as_uint(Kb[col * P1_STRIDE + s * 8 + lq]);
                uint32_t b1 = __float_as_uint(Kb[col * P1_STRIDE + s * 8 + lq + 4]);
                MMA_TF32(acc[nt], afr[s], b0, b1);
            }
        }

#pragma unroll
        for (int nt = 0; nt < 16; nt++) {
            rs0 += ex2a(acc[nt][0]) + ex2a(acc[nt][1]);
            rs1 += ex2a(acc[nt][2]) + ex2a(acc[nt][3]);
        }
        __syncthreads();
    }

    rs0 += __shfl_xor_sync(0xFFFFFFFF, rs0, 1);
    rs0 += __shfl_xor_sync(0xFFFFFFFF, rs0, 2);
    rs1 += __shfl_xor_sync(0xFFFFFFFF, rs1, 1);
    rs1 += __shfl_xor_sync(0xFFFFFFFF, rs1, 2);
    if (lq == 0) {
        g_Linv[bh * NS + q0 + row_lo] = 0.0625f / rs0;
        g_Linv[bh * NS + q0 + row_lo + 8] = 0.0625f / rs1;
    }
}

// ---------------------------------------------------------------------------
// Pass 2: out[b,q,k] = sum_h 2^S_h[q,k] * Linv[bh,q].
//   CTA = (k-tile 128, b*16 + q-tile 128); loops 16 heads, Q&K double-buffered.
//   8 warps, warp = 16x128. oacc 64 + acc 64 + afr 32 regs (~190 total).
// ---------------------------------------------------------------------------
#define P2_STRIDE 68
#define P2_BUF (128 * P2_STRIDE)
#define P2_SMEM_TOTAL (4 * P2_BUF * 4)               // 139,264 B

__global__ __launch_bounds__(256) void pass2_kernel(float* __restrict__ out)
{
    extern __shared__ float p2s[];
    float* Qs = p2s;                      // [2][128][68]
    float* Ks = p2s + 2 * P2_BUF;         // [2][128][68]
    const uint32_t sb_q = smem_u32(Qs);
    const uint32_t sb_k = smem_u32(Ks);

    const int tid = threadIdx.x;
    const int lane = tid & 31, wid = tid >> 5;
    const int lq = lane & 3, lg = lane >> 2;
    const int k0 = blockIdx.x * 128;
    const int b = blockIdx.y >> 4;
    const int q0 = (blockIdx.y & 15) * 128;
    const int row_lo = wid * 16 + lg;

    const int r_ld = tid >> 1, c_ld = (tid & 1) * 32;
    auto prefetch = [&](int st, int h) {
        const size_t base = (size_t)(b * NH + h) * NS;
        uint32_t qs = sb_q + (uint32_t)((st * P2_BUF + r_ld * P2_STRIDE + c_ld) * 4);
        const float* qg = g_Q + (base + q0 + r_ld) * NHD + c_ld;
#pragma unroll
        for (int i = 0; i < 8; i++) cp16(qs + i * 16, qg + i * 4);
        uint32_t ks = sb_k + (uint32_t)((st * P2_BUF + r_ld * P2_STRIDE + c_ld) * 4);
        const float* kg = g_K + (base + k0 + r_ld) * NHD + c_ld;
#pragma unroll
        for (int i = 0; i < 8; i++) cp16(ks + i * 16, kg + i * 4);
    };

    float oacc[16][4];
#pragma unroll
    for (int nt = 0; nt < 16; nt++)
#pragma unroll
        for (int j = 0; j < 4; j++) oacc[nt][j] = 0.0f;

    prefetch(0, 0);
    CP_COMMIT();

    for (int h = 0; h < NH; h++) {
        if (h + 1 < NH) prefetch((h + 1) & 1, h + 1);
        CP_COMMIT();
        CP_WAIT1();
        __syncthreads();

        const float* Qb = Qs + (h & 1) * P2_BUF;
        const float* Kb = Ks + (h & 1) * P2_BUF;

        const float w0 = g_Linv[(b * NH + h) * NS + q0 + row_lo];
        const float w1 = g_Linv[(b * NH + h) * NS + q0 + row_lo + 8];

        uint32_t afr[8][4];
#pragma unroll
        for (int s = 0; s < 8; s++) {
            afr[s][0] = __float_as_uint(Qb[row_lo * P2_STRIDE + s * 8 + lq]);
            afr[s][1] = __float_as_uint(Qb[(row_lo + 8) * P2_STRIDE + s * 8 + lq]);
            afr[s][2] = __float_as_uint(Qb[row_lo * P2_STRIDE + s * 8 + lq + 4]);
            afr[s][3] = __float_as_uint(Qb[(row_lo + 8) * P2_STRIDE + s * 8 + lq + 4]);
        }

        float acc[16][4];
#pragma unroll
        for (int nt = 0; nt < 16; nt++)
#pragma unroll
            for (int j = 0; j < 4; j++) acc[nt][j] = 0.0f;

#pragma unroll
        for (int s = 0; s < 8; s++) {
#pragma unroll
            for (int nt = 0; nt < 16; nt++) {
                const int col = nt * 8 + lg;
                uint32_t b0 = __float_as_uint(Kb[col * P2_STRIDE + s * 8 + lq]);
                uint32_t b1 = __float_as_uint(Kb[col * P2_STRIDE + s * 8 + lq + 4]);
                MMA_TF32(acc[nt], afr[s], b0, b1);
            }
        }

#pragma unroll
        for (int nt = 0; nt < 16; nt++) {
            oacc[nt][0] += ex2a(acc[nt][0]) * w0;
            oacc[nt][1] += ex2a(acc[nt][1]) * w0;
            oacc[nt][2] += ex2a(acc[nt][2]) * w1;
            oacc[nt][3] += ex2a(acc[nt][3]) * w1;
        }
        __syncthreads();
    }

    // Write output tile
    const size_t orow_lo = ((size_t)b * NS + q0 + row_lo) * NS;
    const size_t orow_hi = orow_lo + (size_t)8 * NS;
#pragma unroll
    for (int nt = 0; nt < 16; nt++) {
        int c = k0 + nt * 8 + 2 * lq;
        *(float2*)&out[orow_lo + c] = make_float2(oacc[nt][0], oacc[nt][1]);
        *(float2*)&out[orow_hi + c] = make_float2(oacc[nt][2], oacc[nt][3]);
    }
}

// ---------------------------------------------------------------------------
extern "C" void kernel_launch(void* const* d_in, const int* in_sizes, int n_in,
                              void* d_out, int out_size)
{
    const float* query = (const float*)d_in[0];
    const float* key   = (const float*)d_in[1];
    const float* Wq    = (const float*)d_in[2];
    const float* bq    = (const float*)d_in[3];
    const float* Wk    = (const float*)d_in[4];
    const float* bk    = (const float*)d_in[5];
    float* out = (float*)d_out;

    cudaFuncSetAttribute(proj_mma_kernel,
                         cudaFuncAttributeMaxDynamicSharedMemorySize,
                         PJ_SMEM_TOTAL);
    cudaFuncSetAttribute(pass1_kernel,
                         cudaFuncAttributeMaxDynamicSharedMemorySize,
                         P1_SMEM_TOTAL);
    cudaFuncSetAttribute(pass2_kernel,
                         cudaFuncAttributeMaxDynamicSharedMemorySize,
                         P2_SMEM_TOTAL);

    dim3 pg(ND / 128, (NB * NS) / 128);   // (8, 32)
    proj_mma_kernel<<<pg, 256, PJ_SMEM_TOTAL>>>(query, Wq, bq, QSCALE, 0);
    proj_mma_kernel<<<pg, 256, PJ_SMEM_TOTAL>>>(key,   Wk, bk, 1.0f,   1);
    pass1_kernel<<<dim3(NB * NH, NS / 128), 256, P1_SMEM_TOTAL>>>();
    pass2_kernel<<<dim3(NS / 128, NB * (NS / 128)), 256, P2_SMEM_TOTAL>>>(out);
}

// round 8
// speedup vs baseline: 1.4504x; 1.4504x over previous
#include <cuda_runtime.h>
#include <cuda_fp16.h>
#include <cstdint>

#define NB 2
#define NS 2048
#define ND 1024
#define NH 16
#define NHD 64

// Scratch
__device__ float  g_Q[NB * NH * NS * NHD];            // fp32 [bh, s, hd] (pre-scaled)
__device__ float  g_K[NB * NH * NS * NHD];            // fp32 [bh, s, hd]
__device__ __half g_E[(size_t)NB * NH * NS * NS];     // 268 MB fp16 2^scores
__device__ float  g_Linv[NB * NH * NS];               // 1/(16*rowsum)

// ---------------------------------------------------------------------------
__device__ __forceinline__ uint32_t f2tf(float f) {
    uint32_t u;
    asm("cvt.rna.tf32.f32 %0, %1;" : "=r"(u) : "f"(f));
    return u;
}
__device__ __forceinline__ uint32_t smem_u32(const void* p) {
    uint32_t a;
    asm("{ .reg .u64 t; cvta.to.shared.u64 t, %1; cvt.u32.u64 %0, t; }"
        : "=r"(a) : "l"(p));
    return a;
}
__device__ __forceinline__ void cp16(uint32_t s, const void* g) {
    asm volatile("cp.async.cg.shared.global [%0], [%1], 16;" :: "r"(s), "l"(g));
}
#define CP_COMMIT() asm volatile("cp.async.commit_group;" ::: "memory")
#define CP_WAIT1()  asm volatile("cp.async.wait_group 1;" ::: "memory")

__device__ __forceinline__ float ex2a(float x) {
    float y;
    asm("ex2.approx.f32 %0, %1;" : "=f"(y) : "f"(x));
    return y;
}

#define MMA_TF32(d, a, b0, b1)                                                 \
    asm volatile(                                                              \
        "mma.sync.aligned.m16n8k8.row.col.f32.tf32.tf32.f32 "                  \
        "{%0,%1,%2,%3}, {%4,%5,%6,%7}, {%8,%9}, {%0,%1,%2,%3};"                \
        : "+f"((d)[0]), "+f"((d)[1]), "+f"((d)[2]), "+f"((d)[3])               \
        : "r"((a)[0]), "r"((a)[1]), "r"((a)[2]), "r"((a)[3]),                  \
          "r"(b0), "r"(b1))

// Q scale folds 1/sqrt(64) and log2(e) so softmax uses raw 2^x.
#define QSCALE 0.18033688011112042f

// ---------------------------------------------------------------------------
// Projection GEMM: Out[b,h,s,hd] = (X @ W^T + bias) * scale
//   BM=128, BN=128, BK=32, double-buffered cp.async. 8 warps, warp = 16x128.
//   2 CTAs/SM (smem 73.7KB, regs forced <=128).
// ---------------------------------------------------------------------------
#define PJ_STRIDE 36
#define PJ_BUF (128 * PJ_STRIDE)
#define PJ_SMEM_TOTAL (4 * PJ_BUF * 4)                 // 73,728 B

__global__ __launch_bounds__(256, 2) void proj_mma_kernel(
    const float* __restrict__ X, const float* __restrict__ W,
    const float* __restrict__ bias, float scale, int which)
{
    float* __restrict__ Out = which ? g_K : g_Q;
    extern __shared__ float pjs[];
    float* Xs = pjs;                  // [2][128][36]
    float* Ws = pjs + 2 * PJ_BUF;     // [2][128][36]
    const uint32_t sb_x = smem_u32(Xs);
    const uint32_t sb_w = smem_u32(Ws);

    const int tid = threadIdx.x;
    const int lane = tid & 31, wid = tid >> 5;
    const int lq = lane & 3, lg = lane >> 2;
    const int n0 = blockIdx.x * 128, m0 = blockIdx.y * 128;
    const int row_lo = wid * 16 + lg;

    const int ld_row = tid >> 1;
    const int ld_c0 = (tid & 1) * 16;
    auto prefetch = [&](int st, int kb) {
        uint32_t xs = sb_x + (uint32_t)((st * PJ_BUF + ld_row * PJ_STRIDE + ld_c0) * 4);
        uint32_t ws = sb_w + (uint32_t)((st * PJ_BUF + ld_row * PJ_STRIDE + ld_c0) * 4);
        const float* xg = X + (size_t)(m0 + ld_row) * ND + kb + ld_c0;
        const float* wg = W + (size_t)(n0 + ld_row) * ND + kb + ld_c0;
#pragma unroll
        for (int i = 0; i < 4; i++) {
            cp16(xs + i * 16, xg + i * 4);
            cp16(ws + i * 16, wg + i * 4);
        }
    };

    float acc[16][4];
#pragma unroll
    for (int nt = 0; nt < 16; nt++)
#pragma unroll
        for (int j = 0; j < 4; j++) acc[nt][j] = 0.0f;

    prefetch(0, 0);
    CP_COMMIT();

    for (int kb_i = 0; kb_i < ND / 32; kb_i++) {
        if (kb_i + 1 < ND / 32) prefetch((kb_i + 1) & 1, (kb_i + 1) * 32);
        CP_COMMIT();
        CP_WAIT1();
        __syncthreads();

        const float* Xb = Xs + (kb_i & 1) * PJ_BUF;
        const float* Wb = Ws + (kb_i & 1) * PJ_BUF;
#pragma unroll
        for (int s = 0; s < 4; s++) {
            uint32_t a[4];
            a[0] = __float_as_uint(Xb[row_lo * PJ_STRIDE + s * 8 + lq]);
            a[1] = __float_as_uint(Xb[(row_lo + 8) * PJ_STRIDE + s * 8 + lq]);
            a[2] = __float_as_uint(Xb[row_lo * PJ_STRIDE + s * 8 + lq + 4]);
            a[3] = __float_as_uint(Xb[(row_lo + 8) * PJ_STRIDE + s * 8 + lq + 4]);
#pragma unroll
            for (int nt = 0; nt < 16; nt++) {
                uint32_t b0 = __float_as_uint(Wb[(nt * 8 + lg) * PJ_STRIDE + s * 8 + lq]);
                uint32_t b1 = __float_as_uint(Wb[(nt * 8 + lg) * PJ_STRIDE + s * 8 + lq + 4]);
                MMA_TF32(acc[nt], a, b0, b1);
            }
        }
        __syncthreads();
    }

    // Epilogue: bias + scale, scatter to [bh, s, hd]
    const int m_lo = m0 + row_lo;
    const int b_lo = m_lo >> 11, s_lo = m_lo & 2047;
    const int m_hi = m_lo + 8;
    const int b_hi = m_hi >> 11, s_hi = m_hi & 2047;
#pragma unroll
    for (int nt = 0; nt < 16; nt++) {
        int n = n0 + nt * 8 + 2 * lq;
        float2 bb = *(const float2*)&bias[n];
        int h = n >> 6, hd = n & 63;
        float2 o0, o1;
        o0.x = (acc[nt][0] + bb.x) * scale;
        o0.y = (acc[nt][1] + bb.y) * scale;
        o1.x = (acc[nt][2] + bb.x) * scale;
        o1.y = (acc[nt][3] + bb.y) * scale;
        *(float2*)&Out[((size_t)(b_lo * NH + h) * NS + s_lo) * NHD + hd] = o0;
        *(float2*)&Out[((size_t)(b_hi * NH + h) * NS + s_hi) * NHD + hd] = o1;
    }
}

// ---------------------------------------------------------------------------
// Score kernel (mma.sync tf32, double-buffered K, staged E stores):
//   CTA = (head bh, q-tile 128). 16 key tiles of 128. 8 warps, warp = 16x128.
//   2 CTAs/SM: smem 104.4 KB; the E staging buffer REUSES the Qs tile
//   (after afr extraction each warp's 4352B Qs band is dead; its staging
//   band is the same bytes — warp-private, program-ordered, safe).
// SMEM: Qs[128][68] tf32 (-> stg[8][16][136] half) | Ks[2][128][68] fp32
// ---------------------------------------------------------------------------
#define QS_STRIDE 68
#define KS_OFF    (128 * QS_STRIDE * 4)                   // 34,816 B
#define STG_ROW   136
#define SC_SMEM_TOTAL (KS_OFF + 2 * 128 * QS_STRIDE * 4)  // 104,448 B

__global__ __launch_bounds__(256, 2) void score_kernel()
{
    extern __shared__ char smem[];
    uint32_t* Qs = (uint32_t*)smem;                 // [128][68] tf32
    float* Ks = (float*)(smem + KS_OFF);            // [2][128][68]
    const uint32_t sb_k = smem_u32(Ks);

    const int tid = threadIdx.x;
    const int lane = tid & 31;
    const int wid = tid >> 5;
    const int lq = lane & 3;
    const int lg = lane >> 2;
    const int bh = blockIdx.x;
    const int q0 = blockIdx.y * 128;

    // Staging buffer aliases this warp's (dead after afr) Qs band.
    __half* stg = (__half*)smem + wid * 16 * STG_ROW;

    // K prefetch: 128 rows x 64 floats; 2 threads/row, 8 chunks each
    const int kl_row = tid >> 1;
    const int kl_c0 = (tid & 1) * 32;
    auto prefetch = [&](int st, int kt) {
        uint32_t ks = sb_k + (uint32_t)((st * 128 * QS_STRIDE + kl_row * QS_STRIDE + kl_c0) * 4);
        const float* kg = g_K + ((size_t)bh * NS + kt * 128 + kl_row) * NHD + kl_c0;
#pragma unroll
        for (int i = 0; i < 8; i++) cp16(ks + i * 16, kg + i * 4);
    };

    prefetch(0, 0);
    CP_COMMIT();

    // Stage Q tile -> tf32 smem (rounded)
    const float* __restrict__ Qp = g_Q + ((size_t)bh * NS + q0) * NHD;
#pragma unroll
    for (int t = 0; t < 8; t++) {
        int v = t * 256 + tid;
        int r = v >> 4, c4 = v & 15;
        float4 f = *(const float4*)&Qp[r * NHD + c4 * 4];
        uint4 u = make_uint4(f2tf(f.x), f2tf(f.y), f2tf(f.z), f2tf(f.w));
        *(uint4*)&Qs[r * QS_STRIDE + c4 * 4] = u;
    }
    __syncthreads();

    const int row_lo = wid * 16 + lg;
    uint32_t afr[8][4];
#pragma unroll
    for (int s = 0; s < 8; s++) {
        afr[s][0] = Qs[row_lo * QS_STRIDE + s * 8 + lq];
        afr[s][1] = Qs[(row_lo + 8) * QS_STRIDE + s * 8 + lq];
        afr[s][2] = Qs[row_lo * QS_STRIDE + s * 8 + lq + 4];
        afr[s][3] = Qs[(row_lo + 8) * QS_STRIDE + s * 8 + lq + 4];
    }
    // From here on, this warp's Qs band is reused as its staging buffer.

    float rs0 = 0.0f, rs1 = 0.0f;

    for (int kt = 0; kt < NS / 128; kt++) {
        if (kt + 1 < NS / 128) prefetch((kt + 1) & 1, kt + 1);
        CP_COMMIT();
        CP_WAIT1();
        __syncthreads();

        const float* Kb = Ks + (kt & 1) * 128 * QS_STRIDE;

        float acc[16][4];
#pragma unroll
        for (int nt = 0; nt < 16; nt++)
#pragma unroll
            for (int j = 0; j < 4; j++) acc[nt][j] = 0.0f;

#pragma unroll
        for (int s = 0; s < 8; s++) {
#pragma unroll
            for (int nt = 0; nt < 16; nt++) {
                const int col = nt * 8 + lg;
                uint32_t b0 = __float_as_uint(Kb[col * QS_STRIDE + s * 8 + lq]);
                uint32_t b1 = __float_as_uint(Kb[col * QS_STRIDE + s * 8 + lq + 4]);
                MMA_TF32(acc[nt], afr[s], b0, b1);
            }
        }

        // Epilogue: 2^x -> fp16, stage in (reused) smem, coalesced row stores
#pragma unroll
        for (int nt = 0; nt < 16; nt++) {
            float e0 = ex2a(acc[nt][0]);
            float e1 = ex2a(acc[nt][1]);
            float e2 = ex2a(acc[nt][2]);
            float e3 = ex2a(acc[nt][3]);
            rs0 += e0 + e1;
            rs1 += e2 + e3;
            *(__half2*)&stg[lg * STG_ROW + nt * 8 + 2 * lq] = __floats2half2_rn(e0, e1);
            *(__half2*)&stg[(lg + 8) * STG_ROW + nt * 8 + 2 * lq] = __floats2half2_rn(e2, e3);
        }
        __syncwarp();
#pragma unroll
        for (int r = 0; r < 16; r++) {
            uint2 v = *(uint2*)&stg[r * STG_ROW + lane * 4];
            *(uint2*)&g_E[((size_t)bh * NS + q0 + wid * 16 + r) * NS + kt * 128 + lane * 4] = v;
        }
        __syncwarp();
        __syncthreads();   // done reading Ks[kt&1] before prefetch kt+2 lands
    }

    // Reduce rowsums across the 4 lanes of each group; fold /16 into Linv
    rs0 += __shfl_xor_sync(0xFFFFFFFF, rs0, 1);
    rs0 += __shfl_xor_sync(0xFFFFFFFF, rs0, 2);
    rs1 += __shfl_xor_sync(0xFFFFFFFF, rs1, 1);
    rs1 += __shfl_xor_sync(0xFFFFFFFF, rs1, 2);
    if (lq == 0) {
        g_Linv[bh * NS + q0 + row_lo] = 0.0625f / rs0;
        g_Linv[bh * NS + q0 + row_lo + 8] = 0.0625f / rs1;
    }
}

// ---------------------------------------------------------------------------
// Finalize: out[b,q,k] = sum_h E[b,h,q,k] * Linv[b,h,q]   (pure streaming)
// ---------------------------------------------------------------------------
__global__ __launch_bounds__(256) void finalize_kernel(float* __restrict__ out)
{
    const int tid = threadIdx.x;
    const int bq = blockIdx.x;
    const int b = bq >> 11, q = bq & 2047;

    float acc[8];
#pragma unroll
    for (int j = 0; j < 8; j++) acc[j] = 0.0f;

    for (int h = 0; h < NH; h++) {
        const int bhh = b * NH + h;
        const float w = g_Linv[(bhh << 11) + q];
        const uint4* __restrict__ Ep =
            (const uint4*)(g_E + ((size_t)bhh * NS + q) * NS) + tid;
        uint4 v = *Ep;
        const __half2* hp = (const __half2*)&v;
#pragma unroll
        for (int j = 0; j < 4; j++) {
            float2 f = __half22float2(hp[j]);
            acc[2 * j] += f.x * w;
            acc[2 * j + 1] += f.y * w;
        }
    }

    float4* __restrict__ Op = (float4*)(out + (size_t)bq * NS);
    Op[tid * 2 + 0] = make_float4(acc[0], acc[1], acc[2], acc[3]);
    Op[tid * 2 + 1] = make_float4(acc[4], acc[5], acc[6], acc[7]);
}

// ---------------------------------------------------------------------------
extern "C" void kernel_launch(void* const* d_in, const int* in_sizes, int n_in,
                              void* d_out, int out_size)
{
    const float* query = (const float*)d_in[0];
    const float* key   = (const float*)d_in[1];
    const float* Wq    = (const float*)d_in[2];
    const float* bq    = (const float*)d_in[3];
    const float* Wk    = (const float*)d_in[4];
    const float* bk    = (const float*)d_in[5];
    float* out = (float*)d_out;

    cudaFuncSetAttribute(proj_mma_kernel,
                         cudaFuncAttributeMaxDynamicSharedMemorySize,
                         PJ_SMEM_TOTAL);
    cudaFuncSetAttribute(score_kernel,
                         cudaFuncAttributeMaxDynamicSharedMemorySize,
                         SC_SMEM_TOTAL);

    dim3 pg(ND / 128, (NB * NS) / 128);   // (8, 32)
    proj_mma_kernel<<<pg, 256, PJ_SMEM_TOTAL>>>(query, Wq, bq, QSCALE, 0);
    proj_mma_kernel<<<pg, 256, PJ_SMEM_TOTAL>>>(key,   Wk, bk, 1.0f,   1);
    score_kernel<<<dim3(NB * NH, NS / 128), 256, SC_SMEM_TOTAL>>>();
    finalize_kernel<<<NB * NS, 256>>>(out);
}

// round 9
// speedup vs baseline: 1.7572x; 1.2115x over previous
#include <cuda_runtime.h>
#include <cuda_fp16.h>
#include <cstdint>

#define NB 2
#define NS 2048
#define ND 1024
#define NH 16
#define NHD 64

// Scratch — Q/K projections stored as fp16 (Q pre-scaled by 0.125*log2e).
__device__ __half g_Q[NB * NH * NS * NHD];            // 8.4 MB [bh, s, hd]
__device__ __half g_K[NB * NH * NS * NHD];            // 8.4 MB [bh, s, hd]
__device__ __half g_E[(size_t)NB * NH * NS * NS];     // 268 MB fp16 2^scores
__device__ float  g_Linv[NB * NH * NS];               // 1/(16*rowsum)

// ---------------------------------------------------------------------------
__device__ __forceinline__ uint32_t smem_u32(const void* p) {
    uint32_t a;
    asm("{ .reg .u64 t; cvta.to.shared.u64 t, %1; cvt.u32.u64 %0, t; }"
        : "=r"(a) : "l"(p));
    return a;
}
__device__ __forceinline__ void cp16(uint32_t s, const void* g) {
    asm volatile("cp.async.cg.shared.global [%0], [%1], 16;" :: "r"(s), "l"(g));
}
#define CP_COMMIT() asm volatile("cp.async.commit_group;" ::: "memory")
#define CP_WAIT1()  asm volatile("cp.async.wait_group 1;" ::: "memory")
#define CP_WAIT0()  asm volatile("cp.async.wait_group 0;" ::: "memory")

__device__ __forceinline__ float ex2a(float x) {
    float y;
    asm("ex2.approx.f32 %0, %1;" : "=f"(y) : "f"(x));
    return y;
}

// tf32 mma (projections)
#define MMA_TF32(d, a, b0, b1)                                                 \
    asm volatile(                                                              \
        "mma.sync.aligned.m16n8k8.row.col.f32.tf32.tf32.f32 "                  \
        "{%0,%1,%2,%3}, {%4,%5,%6,%7}, {%8,%9}, {%0,%1,%2,%3};"                \
        : "+f"((d)[0]), "+f"((d)[1]), "+f"((d)[2]), "+f"((d)[3])               \
        : "r"((a)[0]), "r"((a)[1]), "r"((a)[2]), "r"((a)[3]),                  \
          "r"(b0), "r"(b1))

// fp16 mma (scores): m16n8k16, fp32 accumulate
#define MMA_F16(d, a, b0, b1)                                                  \
    asm volatile(                                                              \
        "mma.sync.aligned.m16n8k16.row.col.f32.f16.f16.f32 "                   \
        "{%0,%1,%2,%3}, {%4,%5,%6,%7}, {%8,%9}, {%0,%1,%2,%3};"                \
        : "+f"((d)[0]), "+f"((d)[1]), "+f"((d)[2]), "+f"((d)[3])               \
        : "r"((a)[0]), "r"((a)[1]), "r"((a)[2]), "r"((a)[3]),                  \
          "r"(b0), "r"(b1))

// Q scale folds 1/sqrt(64) and log2(e) so softmax uses raw 2^x.
#define QSCALE 0.18033688011112042f

// ---------------------------------------------------------------------------
// Projection GEMM (tf32): Out_fp16[b,h,s,hd] = (X @ W^T + bias) * scale
//   BM=128, BN=128, BK=32, double-buffered cp.async. 8 warps, warp = 16x128.
// ---------------------------------------------------------------------------
#define PJ_STRIDE 36
#define PJ_BUF (128 * PJ_STRIDE)
#define PJ_SMEM_TOTAL (4 * PJ_BUF * 4)                 // 73,728 B

__global__ __launch_bounds__(256, 2) void proj_mma_kernel(
    const float* __restrict__ X, const float* __restrict__ W,
    const float* __restrict__ bias, float scale, int which)
{
    __half* __restrict__ Out = which ? g_K : g_Q;
    extern __shared__ float pjs[];
    float* Xs = pjs;                  // [2][128][36]
    float* Ws = pjs + 2 * PJ_BUF;     // [2][128][36]
    const uint32_t sb_x = smem_u32(Xs);
    const uint32_t sb_w = smem_u32(Ws);

    const int tid = threadIdx.x;
    const int lane = tid & 31, wid = tid >> 5;
    const int lq = lane & 3, lg = lane >> 2;
    const int n0 = blockIdx.x * 128, m0 = blockIdx.y * 128;
    const int row_lo = wid * 16 + lg;

    const int ld_row = tid >> 1;
    const int ld_c0 = (tid & 1) * 16;
    auto prefetch = [&](int st, int kb) {
        uint32_t xs = sb_x + (uint32_t)((st * PJ_BUF + ld_row * PJ_STRIDE + ld_c0) * 4);
        uint32_t ws = sb_w + (uint32_t)((st * PJ_BUF + ld_row * PJ_STRIDE + ld_c0) * 4);
        const float* xg = X + (size_t)(m0 + ld_row) * ND + kb + ld_c0;
        const float* wg = W + (size_t)(n0 + ld_row) * ND + kb + ld_c0;
#pragma unroll
        for (int i = 0; i < 4; i++) {
            cp16(xs + i * 16, xg + i * 4);
            cp16(ws + i * 16, wg + i * 4);
        }
    };

    float acc[16][4];
#pragma unroll
    for (int nt = 0; nt < 16; nt++)
#pragma unroll
        for (int j = 0; j < 4; j++) acc[nt][j] = 0.0f;

    prefetch(0, 0);
    CP_COMMIT();

    for (int kb_i = 0; kb_i < ND / 32; kb_i++) {
        if (kb_i + 1 < ND / 32) prefetch((kb_i + 1) & 1, (kb_i + 1) * 32);
        CP_COMMIT();
        CP_WAIT1();
        __syncthreads();

        const float* Xb = Xs + (kb_i & 1) * PJ_BUF;
        const float* Wb = Ws + (kb_i & 1) * PJ_BUF;
#pragma unroll
        for (int s = 0; s < 4; s++) {
            uint32_t a[4];
            a[0] = __float_as_uint(Xb[row_lo * PJ_STRIDE + s * 8 + lq]);
            a[1] = __float_as_uint(Xb[(row_lo + 8) * PJ_STRIDE + s * 8 + lq]);
            a[2] = __float_as_uint(Xb[row_lo * PJ_STRIDE + s * 8 + lq + 4]);
            a[3] = __float_as_uint(Xb[(row_lo + 8) * PJ_STRIDE + s * 8 + lq + 4]);
#pragma unroll
            for (int nt = 0; nt < 16; nt++) {
                uint32_t b0 = __float_as_uint(Wb[(nt * 8 + lg) * PJ_STRIDE + s * 8 + lq]);
                uint32_t b1 = __float_as_uint(Wb[(nt * 8 + lg) * PJ_STRIDE + s * 8 + lq + 4]);
                MMA_TF32(acc[nt], a, b0, b1);
            }
        }
        __syncthreads();
    }

    // Epilogue: bias + scale, convert fp16, scatter to [bh, s, hd]
    const int m_lo = m0 + row_lo;
    const int b_lo = m_lo >> 11, s_lo = m_lo & 2047;
    const int m_hi = m_lo + 8;
    const int b_hi = m_hi >> 11, s_hi = m_hi & 2047;
#pragma unroll
    for (int nt = 0; nt < 16; nt++) {
        int n = n0 + nt * 8 + 2 * lq;
        float2 bb = *(const float2*)&bias[n];
        int h = n >> 6, hd = n & 63;
        __half2 o0 = __floats2half2_rn((acc[nt][0] + bb.x) * scale,
                                       (acc[nt][1] + bb.y) * scale);
        __half2 o1 = __floats2half2_rn((acc[nt][2] + bb.x) * scale,
                                       (acc[nt][3] + bb.y) * scale);
        *(__half2*)&Out[((size_t)(b_lo * NH + h) * NS + s_lo) * NHD + hd] = o0;
        *(__half2*)&Out[((size_t)(b_hi * NH + h) * NS + s_hi) * NHD + hd] = o1;
    }
}

// ---------------------------------------------------------------------------
// Score kernel (fp16 mma m16n8k16, double-buffered K, staged E stores):
//   CTA = (head bh, q-tile 128). 16 key tiles of 128. 8 warps, warp = 16x128.
//   Per warp-tile: 64 HMMA + 128 LDS.32 (B frags) — half of the tf32 version.
// SMEM: Qs[128][72]h | Ks[2][128][72]h | stg[8][16][136]h   = 90,112 B
//   (stride 72 halves -> b-frag bank = 4*lg+lq, conflict-free)
// ---------------------------------------------------------------------------
#define QS_H 72
#define KS_OFF  (128 * QS_H * 2)                       // 18,432 B
#define STG_OFF (KS_OFF + 2 * 128 * QS_H * 2)          // 55,296 B
#define STG_ROW 136
#define SC_SMEM_TOTAL (STG_OFF + 8 * 16 * STG_ROW * 2) // 90,112 B

__global__ __launch_bounds__(256, 2) void score_kernel()
{
    extern __shared__ char smem[];
    __half* Qs = (__half*)smem;                     // [128][72]
    __half* Ks = (__half*)(smem + KS_OFF);          // [2][128][72]
    __half* stgall = (__half*)(smem + STG_OFF);
    const uint32_t sb_q = smem_u32(Qs);
    const uint32_t sb_k = smem_u32(Ks);

    const int tid = threadIdx.x;
    const int lane = tid & 31;
    const int wid = tid >> 5;
    const int lq = lane & 3;
    const int lg = lane >> 2;
    const int bh = blockIdx.x;
    const int q0 = blockIdx.y * 128;

    __half* stg = stgall + wid * 16 * STG_ROW;

    // K/Q staging: 128 rows x 128 B; 2 threads/row, 4 cp16 each
    const int r_ld = tid >> 1;
    const int c_ld = (tid & 1) * 32;                // half-index base
    auto prefetchK = [&](int st, int kt) {
        uint32_t ks = sb_k + (uint32_t)((st * 128 * QS_H + r_ld * QS_H + c_ld) * 2);
        const __half* kg = g_K + ((size_t)bh * NS + kt * 128 + r_ld) * NHD + c_ld;
#pragma unroll
        for (int i = 0; i < 4; i++) cp16(ks + i * 16, kg + i * 8);
    };

    prefetchK(0, 0);
    CP_COMMIT();
    {
        uint32_t qs = sb_q + (uint32_t)((r_ld * QS_H + c_ld) * 2);
        const __half* qg = g_Q + ((size_t)bh * NS + q0 + r_ld) * NHD + c_ld;
#pragma unroll
        for (int i = 0; i < 4; i++) cp16(qs + i * 16, qg + i * 8);
    }
    CP_COMMIT();
    CP_WAIT0();
    __syncthreads();

    // A fragments: 4 k16-steps over hd=64; 16 regs total
    const int row_lo = wid * 16 + lg;
    uint32_t afr[4][4];
#pragma unroll
    for (int s = 0; s < 4; s++) {
        afr[s][0] = *(uint32_t*)&Qs[row_lo * QS_H + s * 16 + 2 * lq];
        afr[s][1] = *(uint32_t*)&Qs[(row_lo + 8) * QS_H + s * 16 + 2 * lq];
        afr[s][2] = *(uint32_t*)&Qs[row_lo * QS_H + s * 16 + 2 * lq + 8];
        afr[s][3] = *(uint32_t*)&Qs[(row_lo + 8) * QS_H + s * 16 + 2 * lq + 8];
    }

    float rs0 = 0.0f, rs1 = 0.0f;

    for (int kt = 0; kt < NS / 128; kt++) {
        if (kt + 1 < NS / 128) prefetchK((kt + 1) & 1, kt + 1);
        CP_COMMIT();
        CP_WAIT1();
        __syncthreads();

        const __half* Kb = Ks + (kt & 1) * 128 * QS_H;

        float acc[16][4];
#pragma unroll
        for (int nt = 0; nt < 16; nt++)
#pragma unroll
            for (int j = 0; j < 4; j++) acc[nt][j] = 0.0f;

#pragma unroll
        for (int s = 0; s < 4; s++) {
#pragma unroll
            for (int nt = 0; nt < 16; nt++) {
                const int col = nt * 8 + lg;
                uint32_t b0 = *(uint32_t*)&Kb[col * QS_H + s * 16 + 2 * lq];
                uint32_t b1 = *(uint32_t*)&Kb[col * QS_H + s * 16 + 2 * lq + 8];
                MMA_F16(acc[nt], afr[s], b0, b1);
            }
        }

        // Epilogue: 2^x -> fp16, stage in smem, coalesced row stores
#pragma unroll
        for (int nt = 0; nt < 16; nt++) {
            float e0 = ex2a(acc[nt][0]);
            float e1 = ex2a(acc[nt][1]);
            float e2 = ex2a(acc[nt][2]);
            float e3 = ex2a(acc[nt][3]);
            rs0 += e0 + e1;
            rs1 += e2 + e3;
            *(__half2*)&stg[lg * STG_ROW + nt * 8 + 2 * lq] = __floats2half2_rn(e0, e1);
            *(__half2*)&stg[(lg + 8) * STG_ROW + nt * 8 + 2 * lq] = __floats2half2_rn(e2, e3);
        }
        __syncwarp();
#pragma unroll
        for (int r = 0; r < 16; r++) {
            uint2 v = *(uint2*)&stg[r * STG_ROW + lane * 4];
            *(uint2*)&g_E[((size_t)bh * NS + q0 + wid * 16 + r) * NS + kt * 128 + lane * 4] = v;
        }
        __syncwarp();
        __syncthreads();   // all warps done with Ks[kt&1] before it is refilled
    }

    // Rowsum reduce (4 lanes per group); fold /16 into Linv
    rs0 += __shfl_xor_sync(0xFFFFFFFF, rs0, 1);
    rs0 += __shfl_xor_sync(0xFFFFFFFF, rs0, 2);
    rs1 += __shfl_xor_sync(0xFFFFFFFF, rs1, 1);
    rs1 += __shfl_xor_sync(0xFFFFFFFF, rs1, 2);
    if (lq == 0) {
        g_Linv[bh * NS + q0 + row_lo] = 0.0625f / rs0;
        g_Linv[bh * NS + q0 + row_lo + 8] = 0.0625f / rs1;
    }
}

// ---------------------------------------------------------------------------
// Finalize: out[b,q,k] = sum_h E[b,h,q,k] * Linv[b,h,q]   (pure streaming)
// ---------------------------------------------------------------------------
__global__ __launch_bounds__(256) void finalize_kernel(float* __restrict__ out)
{
    const int tid = threadIdx.x;
    const int bq = blockIdx.x;
    const int b = bq >> 11, q = bq & 2047;

    float acc[8];
#pragma unroll
    for (int j = 0; j < 8; j++) acc[j] = 0.0f;

    for (int h = 0; h < NH; h++) {
        const int bhh = b * NH + h;
        const float w = g_Linv[(bhh << 11) + q];
        const uint4* __restrict__ Ep =
            (const uint4*)(g_E + ((size_t)bhh * NS + q) * NS) + tid;
        uint4 v = *Ep;
        const __half2* hp = (const __half2*)&v;
#pragma unroll
        for (int j = 0; j < 4; j++) {
            float2 f = __half22float2(hp[j]);
            acc[2 * j] += f.x * w;
            acc[2 * j + 1] += f.y * w;
        }
    }

    float4* __restrict__ Op = (float4*)(out + (size_t)bq * NS);
    Op[tid * 2 + 0] = make_float4(acc[0], acc[1], acc[2], acc[3]);
    Op[tid * 2 + 1] = make_float4(acc[4], acc[5], acc[6], acc[7]);
}

// ---------------------------------------------------------------------------
extern "C" void kernel_launch(void* const* d_in, const int* in_sizes, int n_in,
                              void* d_out, int out_size)
{
    const float* query = (const float*)d_in[0];
    const float* key   = (const float*)d_in[1];
    const float* Wq    = (const float*)d_in[2];
    const float* bq    = (const float*)d_in[3];
    const float* Wk    = (const float*)d_in[4];
    const float* bk    = (const float*)d_in[5];
    float* out = (float*)d_out;

    cudaFuncSetAttribute(proj_mma_kernel,
                         cudaFuncAttributeMaxDynamicSharedMemorySize,
                         PJ_SMEM_TOTAL);
    cudaFuncSetAttribute(score_kernel,
                         cudaFuncAttributeMaxDynamicSharedMemorySize,
                         SC_SMEM_TOTAL);

    dim3 pg(ND / 128, (NB * NS) / 128);   // (8, 32)
    proj_mma_kernel<<<pg, 256, PJ_SMEM_TOTAL>>>(query, Wq, bq, QSCALE, 0);
    proj_mma_kernel<<<pg, 256, PJ_SMEM_TOTAL>>>(key,   Wk, bk, 1.0f,   1);
    score_kernel<<<dim3(NB * NH, NS / 128), 256, SC_SMEM_TOTAL>>>();
    finalize_kernel<<<NB * NS, 256>>>(out);
}

// round 10
// speedup vs baseline: 2.1768x; 1.2388x over previous
#include <cuda_runtime.h>
#include <cuda_fp16.h>
#include <cstdint>

#define NB 2
#define NS 2048
#define ND 1024
#define NH 16
#define NHD 64

// fp16 copies of the inputs (filled by cvt_kernel)
__device__ __half g_hQin[NB * NS * ND];               // 8.4 MB
__device__ __half g_hKin[NB * NS * ND];               // 8.4 MB
__device__ __half g_hWq[ND * ND];                     // 2.1 MB
__device__ __half g_hWk[ND * ND];                     // 2.1 MB

// Scratch — Q/K projections stored as fp16 (Q pre-scaled by 0.125*log2e).
__device__ __half g_Q[NB * NH * NS * NHD];            // 8.4 MB [bh, s, hd]
__device__ __half g_K[NB * NH * NS * NHD];            // 8.4 MB [bh, s, hd]
__device__ __half g_E[(size_t)NB * NH * NS * NS];     // 268 MB fp16 2^scores
__device__ float  g_Linv[NB * NH * NS];               // 1/(16*rowsum)

// ---------------------------------------------------------------------------
__device__ __forceinline__ uint32_t smem_u32(const void* p) {
    uint32_t a;
    asm("{ .reg .u64 t; cvta.to.shared.u64 t, %1; cvt.u32.u64 %0, t; }"
        : "=r"(a) : "l"(p));
    return a;
}
__device__ __forceinline__ void cp16(uint32_t s, const void* g) {
    asm volatile("cp.async.cg.shared.global [%0], [%1], 16;" :: "r"(s), "l"(g));
}
#define CP_COMMIT() asm volatile("cp.async.commit_group;" ::: "memory")
#define CP_WAIT1()  asm volatile("cp.async.wait_group 1;" ::: "memory")
#define CP_WAIT0()  asm volatile("cp.async.wait_group 0;" ::: "memory")

__device__ __forceinline__ float ex2a(float x) {
    float y;
    asm("ex2.approx.f32 %0, %1;" : "=f"(y) : "f"(x));
    return y;
}

// fp16 mma: m16n8k16, fp32 accumulate
#define MMA_F16(d, a, b0, b1)                                                  \
    asm volatile(                                                              \
        "mma.sync.aligned.m16n8k16.row.col.f32.f16.f16.f32 "                   \
        "{%0,%1,%2,%3}, {%4,%5,%6,%7}, {%8,%9}, {%0,%1,%2,%3};"                \
        : "+f"((d)[0]), "+f"((d)[1]), "+f"((d)[2]), "+f"((d)[3])               \
        : "r"((a)[0]), "r"((a)[1]), "r"((a)[2]), "r"((a)[3]),                  \
          "r"(b0), "r"(b1))

// Q scale folds 1/sqrt(64) and log2(e) so softmax uses raw 2^x.
#define QSCALE 0.18033688011112042f

// ---------------------------------------------------------------------------
// cvt kernel: fp32 inputs -> fp16 buffers. Each thread: 8 elements.
// Segments: qin 4.19M | kin 4.19M | Wq 1.05M | Wk 1.05M  (all /8 aligned)
// ---------------------------------------------------------------------------
#define CVT_TOTAL (NB * NS * ND * 2 + ND * ND * 2)     // 10,485,760

__global__ __launch_bounds__(256) void cvt_kernel(
    const float* __restrict__ q, const float* __restrict__ k,
    const float* __restrict__ wq, const float* __restrict__ wk)
{
    const int idx = (blockIdx.x * 256 + threadIdx.x) * 8;
    const float* src;
    __half* dst;
    int off;
    if (idx < NB * NS * ND) {
        src = q; dst = g_hQin; off = idx;
    } else if (idx < 2 * NB * NS * ND) {
        src = k; dst = g_hKin; off = idx - NB * NS * ND;
    } else if (idx < 2 * NB * NS * ND + ND * ND) {
        src = wq; dst = g_hWq; off = idx - 2 * NB * NS * ND;
    } else {
        src = wk; dst = g_hWk; off = idx - 2 * NB * NS * ND - ND * ND;
    }
    float4 f0 = *(const float4*)(src + off);
    float4 f1 = *(const float4*)(src + off + 4);
    uint2 o0, o1;
    *(__half2*)&o0.x = __floats2half2_rn(f0.x, f0.y);
    *(__half2*)&o0.y = __floats2half2_rn(f0.z, f0.w);
    *(__half2*)&o1.x = __floats2half2_rn(f1.x, f1.y);
    *(__half2*)&o1.y = __floats2half2_rn(f1.z, f1.w);
    *(uint4*)(dst + off) = make_uint4(o0.x, o0.y, o1.x, o1.y);
}

// ---------------------------------------------------------------------------
// Projection GEMM (fp16 mma): Out_fp16[b,h,s,hd] = (X @ W^T + bias) * scale
//   Fused Q & K via blockIdx.z. BM=128, BN=128, BK=32, double-buffered
//   cp.async. 8 warps, warp = 16x128. Per k-iter: 32 HMMA (2 k16 steps).
//   smem stride 40 halves -> all fragment LDS conflict-free.
// ---------------------------------------------------------------------------
#define PJ_H 40
#define PJ_BUF (128 * PJ_H)                            // halves per buffer
#define PJ_SMEM_TOTAL (4 * PJ_BUF * 2)                 // 40,960 B

__global__ __launch_bounds__(256, 2) void proj_mma_kernel(
    const float* __restrict__ bq_in, const float* __restrict__ bk_in)
{
    const int z = blockIdx.z;
    const __half* __restrict__ X = z ? g_hKin : g_hQin;
    const __half* __restrict__ W = z ? g_hWk : g_hWq;
    const float* __restrict__ bias = z ? bk_in : bq_in;
    const float scale = z ? 1.0f : QSCALE;
    __half* __restrict__ Out = z ? g_K : g_Q;

    extern __shared__ __half pjs[];
    __half* Xs = pjs;                  // [2][128][40]
    __half* Ws = pjs + 2 * PJ_BUF;     // [2][128][40]
    const uint32_t sb_x = smem_u32(Xs);
    const uint32_t sb_w = smem_u32(Ws);

    const int tid = threadIdx.x;
    const int lane = tid & 31, wid = tid >> 5;
    const int lq = lane & 3, lg = lane >> 2;
    const int n0 = blockIdx.x * 128, m0 = blockIdx.y * 128;
    const int row_lo = wid * 16 + lg;

    // X: threads 0-127 stage row t (4 cp16); W: threads 128-255 row t-128.
    auto prefetch = [&](int st, int kb) {
        if (tid < 128) {
            uint32_t xs = sb_x + (uint32_t)((st * PJ_BUF + tid * PJ_H) * 2);
            const __half* xg = X + (size_t)(m0 + tid) * ND + kb;
#pragma unroll
            for (int i = 0; i < 4; i++) cp16(xs + i * 16, xg + i * 8);
        } else {
            int r = tid - 128;
            uint32_t ws = sb_w + (uint32_t)((st * PJ_BUF + r * PJ_H) * 2);
            const __half* wg = W + (size_t)(n0 + r) * ND + kb;
#pragma unroll
            for (int i = 0; i < 4; i++) cp16(ws + i * 16, wg + i * 8);
        }
    };

    float acc[16][4];
#pragma unroll
    for (int nt = 0; nt < 16; nt++)
#pragma unroll
        for (int j = 0; j < 4; j++) acc[nt][j] = 0.0f;

    prefetch(0, 0);
    CP_COMMIT();

    for (int kb_i = 0; kb_i < ND / 32; kb_i++) {
        if (kb_i + 1 < ND / 32) prefetch((kb_i + 1) & 1, (kb_i + 1) * 32);
        CP_COMMIT();
        CP_WAIT1();
        __syncthreads();

        const __half* Xb = Xs + (kb_i & 1) * PJ_BUF;
        const __half* Wb = Ws + (kb_i & 1) * PJ_BUF;
#pragma unroll
        for (int s = 0; s < 2; s++) {
            uint32_t a[4];
            a[0] = *(uint32_t*)&Xb[row_lo * PJ_H + s * 16 + 2 * lq];
            a[1] = *(uint32_t*)&Xb[(row_lo + 8) * PJ_H + s * 16 + 2 * lq];
            a[2] = *(uint32_t*)&Xb[row_lo * PJ_H + s * 16 + 2 * lq + 8];
            a[3] = *(uint32_t*)&Xb[(row_lo + 8) * PJ_H + s * 16 + 2 * lq + 8];
#pragma unroll
            for (int nt = 0; nt < 16; nt++) {
                const int col = nt * 8 + lg;
                uint32_t b0 = *(uint32_t*)&Wb[col * PJ_H + s * 16 + 2 * lq];
                uint32_t b1 = *(uint32_t*)&Wb[col * PJ_H + s * 16 + 2 * lq + 8];
                MMA_F16(acc[nt], a, b0, b1);
            }
        }
        __syncthreads();
    }

    // Epilogue: bias + scale, convert fp16, scatter to [bh, s, hd]
    const int m_lo = m0 + row_lo;
    const int b_lo = m_lo >> 11, s_lo = m_lo & 2047;
    const int m_hi = m_lo + 8;
    const int b_hi = m_hi >> 11, s_hi = m_hi & 2047;
#pragma unroll
    for (int nt = 0; nt < 16; nt++) {
        int n = n0 + nt * 8 + 2 * lq;
        float2 bb = *(const float2*)&bias[n];
        int h = n >> 6, hd = n & 63;
        __half2 o0 = __floats2half2_rn((acc[nt][0] + bb.x) * scale,
                                       (acc[nt][1] + bb.y) * scale);
        __half2 o1 = __floats2half2_rn((acc[nt][2] + bb.x) * scale,
                                       (acc[nt][3] + bb.y) * scale);
        *(__half2*)&Out[((size_t)(b_lo * NH + h) * NS + s_lo) * NHD + hd] = o0;
        *(__half2*)&Out[((size_t)(b_hi * NH + h) * NS + s_hi) * NHD + hd] = o1;
    }
}

// ---------------------------------------------------------------------------
// Score kernel (fp16 mma m16n8k16, double-buffered K, staged E stores):
//   CTA = (head bh, q-tile 128). 16 key tiles of 128. 8 warps, warp = 16x128.
// SMEM: Qs[128][72]h | Ks[2][128][72]h | stg[8][16][136]h   = 90,112 B
// ---------------------------------------------------------------------------
#define QS_H 72
#define KS_OFF  (128 * QS_H * 2)                       // 18,432 B
#define STG_OFF (KS_OFF + 2 * 128 * QS_H * 2)          // 55,296 B
#define STG_ROW 136
#define SC_SMEM_TOTAL (STG_OFF + 8 * 16 * STG_ROW * 2) // 90,112 B

__global__ __launch_bounds__(256, 2) void score_kernel()
{
    extern __shared__ char smem[];
    __half* Qs = (__half*)smem;                     // [128][72]
    __half* Ks = (__half*)(smem + KS_OFF);          // [2][128][72]
    __half* stgall = (__half*)(smem + STG_OFF);
    const uint32_t sb_q = smem_u32(Qs);
    const uint32_t sb_k = smem_u32(Ks);

    const int tid = threadIdx.x;
    const int lane = tid & 31;
    const int wid = tid >> 5;
    const int lq = lane & 3;
    const int lg = lane >> 2;
    const int bh = blockIdx.x;
    const int q0 = blockIdx.y * 128;

    __half* stg = stgall + wid * 16 * STG_ROW;

    const int r_ld = tid >> 1;
    const int c_ld = (tid & 1) * 32;
    auto prefetchK = [&](int st, int kt) {
        uint32_t ks = sb_k + (uint32_t)((st * 128 * QS_H + r_ld * QS_H + c_ld) * 2);
        const __half* kg = g_K + ((size_t)bh * NS + kt * 128 + r_ld) * NHD + c_ld;
#pragma unroll
        for (int i = 0; i < 4; i++) cp16(ks + i * 16, kg + i * 8);
    };

    prefetchK(0, 0);
    CP_COMMIT();
    {
        uint32_t qs = sb_q + (uint32_t)((r_ld * QS_H + c_ld) * 2);
        const __half* qg = g_Q + ((size_t)bh * NS + q0 + r_ld) * NHD + c_ld;
#pragma unroll
        for (int i = 0; i < 4; i++) cp16(qs + i * 16, qg + i * 8);
    }
    CP_COMMIT();
    CP_WAIT0();
    __syncthreads();

    const int row_lo = wid * 16 + lg;
    uint32_t afr[4][4];
#pragma unroll
    for (int s = 0; s < 4; s++) {
        afr[s][0] = *(uint32_t*)&Qs[row_lo * QS_H + s * 16 + 2 * lq];
        afr[s][1] = *(uint32_t*)&Qs[(row_lo + 8) * QS_H + s * 16 + 2 * lq];
        afr[s][2] = *(uint32_t*)&Qs[row_lo * QS_H + s * 16 + 2 * lq + 8];
        afr[s][3] = *(uint32_t*)&Qs[(row_lo + 8) * QS_H + s * 16 + 2 * lq + 8];
    }

    float rs0 = 0.0f, rs1 = 0.0f;

    for (int kt = 0; kt < NS / 128; kt++) {
        if (kt + 1 < NS / 128) prefetchK((kt + 1) & 1, kt + 1);
        CP_COMMIT();
        CP_WAIT1();
        __syncthreads();

        const __half* Kb = Ks + (kt & 1) * 128 * QS_H;

        float acc[16][4];
#pragma unroll
        for (int nt = 0; nt < 16; nt++)
#pragma unroll
            for (int j = 0; j < 4; j++) acc[nt][j] = 0.0f;

#pragma unroll
        for (int s = 0; s < 4; s++) {
#pragma unroll
            for (int nt = 0; nt < 16; nt++) {
                const int col = nt * 8 + lg;
                uint32_t b0 = *(uint32_t*)&Kb[col * QS_H + s * 16 + 2 * lq];
                uint32_t b1 = *(uint32_t*)&Kb[col * QS_H + s * 16 + 2 * lq + 8];
                MMA_F16(acc[nt], afr[s], b0, b1);
            }
        }

#pragma unroll
        for (int nt = 0; nt < 16; nt++) {
            float e0 = ex2a(acc[nt][0]);
            float e1 = ex2a(acc[nt][1]);
            float e2 = ex2a(acc[nt][2]);
            float e3 = ex2a(acc[nt][3]);
            rs0 += e0 + e1;
            rs1 += e2 + e3;
            *(__half2*)&stg[lg * STG_ROW + nt * 8 + 2 * lq] = __floats2half2_rn(e0, e1);
            *(__half2*)&stg[(lg + 8) * STG_ROW + nt * 8 + 2 * lq] = __floats2half2_rn(e2, e3);
        }
        __syncwarp();
#pragma unroll
        for (int r = 0; r < 16; r++) {
            uint2 v = *(uint2*)&stg[r * STG_ROW + lane * 4];
            *(uint2*)&g_E[((size_t)bh * NS + q0 + wid * 16 + r) * NS + kt * 128 + lane * 4] = v;
        }
        __syncwarp();
        __syncthreads();
    }

    rs0 += __shfl_xor_sync(0xFFFFFFFF, rs0, 1);
    rs0 += __shfl_xor_sync(0xFFFFFFFF, rs0, 2);
    rs1 += __shfl_xor_sync(0xFFFFFFFF, rs1, 1);
    rs1 += __shfl_xor_sync(0xFFFFFFFF, rs1, 2);
    if (lq == 0) {
        g_Linv[bh * NS + q0 + row_lo] = 0.0625f / rs0;
        g_Linv[bh * NS + q0 + row_lo + 8] = 0.0625f / rs1;
    }
}

// ---------------------------------------------------------------------------
// Finalize: out[b,q,k] = sum_h E[b,h,q,k] * Linv[b,h,q]   (pure streaming)
// ---------------------------------------------------------------------------
__global__ __launch_bounds__(256) void finalize_kernel(float* __restrict__ out)
{
    const int tid = threadIdx.x;
    const int bq = blockIdx.x;
    const int b = bq >> 11, q = bq & 2047;

    float acc[8];
#pragma unroll
    for (int j = 0; j < 8; j++) acc[j] = 0.0f;

    for (int h = 0; h < NH; h++) {
        const int bhh = b * NH + h;
        const float w = g_Linv[(bhh << 11) + q];
        const uint4* __restrict__ Ep =
            (const uint4*)(g_E + ((size_t)bhh * NS + q) * NS) + tid;
        uint4 v = *Ep;
        const __half2* hp = (const __half2*)&v;
#pragma unroll
        for (int j = 0; j < 4; j++) {
            float2 f = __half22float2(hp[j]);
            acc[2 * j] += f.x * w;
            acc[2 * j + 1] += f.y * w;
        }
    }

    float4* __restrict__ Op = (float4*)(out + (size_t)bq * NS);
    Op[tid * 2 + 0] = make_float4(acc[0], acc[1], acc[2], acc[3]);
    Op[tid * 2 + 1] = make_float4(acc[4], acc[5], acc[6], acc[7]);
}

// ---------------------------------------------------------------------------
extern "C" void kernel_launch(void* const* d_in, const int* in_sizes, int n_in,
                              void* d_out, int out_size)
{
    const float* query = (const float*)d_in[0];
    const float* key   = (const float*)d_in[1];
    const float* Wq    = (const float*)d_in[2];
    const float* bq    = (const float*)d_in[3];
    const float* Wk    = (const float*)d_in[4];
    const float* bk    = (const float*)d_in[5];
    float* out = (float*)d_out;

    cudaFuncSetAttribute(proj_mma_kernel,
                         cudaFuncAttributeMaxDynamicSharedMemorySize,
                         PJ_SMEM_TOTAL);
    cudaFuncSetAttribute(score_kernel,
                         cudaFuncAttributeMaxDynamicSharedMemorySize,
                         SC_SMEM_TOTAL);

    cvt_kernel<<<CVT_TOTAL / (256 * 8), 256>>>(query, key, Wq, Wk);
    proj_mma_kernel<<<dim3(ND / 128, (NB * NS) / 128, 2), 256, PJ_SMEM_TOTAL>>>(bq, bk);
    score_kernel<<<dim3(NB * NH, NS / 128), 256, SC_SMEM_TOTAL>>>();
    finalize_kernel<<<NB * NS, 256>>>(out);
}

// round 11
// speedup vs baseline: 2.3234x; 1.0674x over previous
#include <cuda_runtime.h>
#include <cuda_fp16.h>
#include <cstdint>

#define NB 2
#define NS 2048
#define ND 1024
#define NH 16
#define NHD 64

// fp16 copies of the inputs (filled by cvt_kernel)
__device__ __half g_hQin[NB * NS * ND];               // 8.4 MB
__device__ __half g_hKin[NB * NS * ND];               // 8.4 MB
__device__ __half g_hWq[ND * ND];                     // 2.1 MB
__device__ __half g_hWk[ND * ND];                     // 2.1 MB

// Scratch — Q/K projections stored as fp16 (Q pre-scaled by 0.125*log2e).
__device__ __half g_Q[NB * NH * NS * NHD];            // 8.4 MB [bh, s, hd]
__device__ __half g_K[NB * NH * NS * NHD];            // 8.4 MB [bh, s, hd]
__device__ __half g_E[(size_t)NB * NH * NS * NS];     // 268 MB fp16 2^scores
__device__ float  g_Linv[NB * NH * NS];               // 1/(16*rowsum)

// ---------------------------------------------------------------------------
__device__ __forceinline__ uint32_t smem_u32(const void* p) {
    uint32_t a;
    asm("{ .reg .u64 t; cvta.to.shared.u64 t, %1; cvt.u32.u64 %0, t; }"
        : "=r"(a) : "l"(p));
    return a;
}
__device__ __forceinline__ void cp16(uint32_t s, const void* g) {
    asm volatile("cp.async.cg.shared.global [%0], [%1], 16;" :: "r"(s), "l"(g));
}
#define CP_COMMIT() asm volatile("cp.async.commit_group;" ::: "memory")
#define CP_WAIT1()  asm volatile("cp.async.wait_group 1;" ::: "memory")
#define CP_WAIT0()  asm volatile("cp.async.wait_group 0;" ::: "memory")

__device__ __forceinline__ float ex2a(float x) {
    float y;
    asm("ex2.approx.f32 %0, %1;" : "=f"(y) : "f"(x));
    return y;
}

// fp16 mma: m16n8k16, fp32 accumulate
#define MMA_F16(d, a, b0, b1)                                                  \
    asm volatile(                                                              \
        "mma.sync.aligned.m16n8k16.row.col.f32.f16.f16.f32 "                   \
        "{%0,%1,%2,%3}, {%4,%5,%6,%7}, {%8,%9}, {%0,%1,%2,%3};"                \
        : "+f"((d)[0]), "+f"((d)[1]), "+f"((d)[2]), "+f"((d)[3])               \
        : "r"((a)[0]), "r"((a)[1]), "r"((a)[2]), "r"((a)[3]),                  \
          "r"(b0), "r"(b1))

#define LDSM_X4(r, addr)                                                       \
    asm volatile("ldmatrix.sync.aligned.m8n8.x4.shared.b16 {%0,%1,%2,%3}, [%4];" \
        : "=r"((r)[0]), "=r"((r)[1]), "=r"((r)[2]), "=r"((r)[3]) : "r"(addr))

#define STSM_X4(addr, r0, r1, r2, r3)                                          \
    asm volatile("stmatrix.sync.aligned.m8n8.x4.shared.b16 [%0], {%1,%2,%3,%4};" \
        :: "r"(addr), "r"(r0), "r"(r1), "r"(r2), "r"(r3) : "memory")

// Q scale folds 1/sqrt(64) and log2(e) so softmax uses raw 2^x.
#define QSCALE 0.18033688011112042f

// ---------------------------------------------------------------------------
// cvt kernel: fp32 inputs -> fp16 buffers. Each thread: 8 elements.
// ---------------------------------------------------------------------------
#define CVT_TOTAL (NB * NS * ND * 2 + ND * ND * 2)     // 10,485,760

__global__ __launch_bounds__(256) void cvt_kernel(
    const float* __restrict__ q, const float* __restrict__ k,
    const float* __restrict__ wq, const float* __restrict__ wk)
{
    const int idx = (blockIdx.x * 256 + threadIdx.x) * 8;
    const float* src;
    __half* dst;
    int off;
    if (idx < NB * NS * ND) {
        src = q; dst = g_hQin; off = idx;
    } else if (idx < 2 * NB * NS * ND) {
        src = k; dst = g_hKin; off = idx - NB * NS * ND;
    } else if (idx < 2 * NB * NS * ND + ND * ND) {
        src = wq; dst = g_hWq; off = idx - 2 * NB * NS * ND;
    } else {
        src = wk; dst = g_hWk; off = idx - 2 * NB * NS * ND - ND * ND;
    }
    float4 f0 = *(const float4*)(src + off);
    float4 f1 = *(const float4*)(src + off + 4);
    uint2 o0, o1;
    *(__half2*)&o0.x = __floats2half2_rn(f0.x, f0.y);
    *(__half2*)&o0.y = __floats2half2_rn(f0.z, f0.w);
    *(__half2*)&o1.x = __floats2half2_rn(f1.x, f1.y);
    *(__half2*)&o1.y = __floats2half2_rn(f1.z, f1.w);
    *(uint4*)(dst + off) = make_uint4(o0.x, o0.y, o1.x, o1.y);
}

// ---------------------------------------------------------------------------
// Projection GEMM (fp16 mma + ldmatrix): Out = (X @ W^T + bias) * scale
//   Fused Q & K via blockIdx.z. BM=128, BN=128, BK=32, double-buffered.
// ---------------------------------------------------------------------------
#define PJ_H 40
#define PJ_BUF (128 * PJ_H)
#define PJ_SMEM_TOTAL (4 * PJ_BUF * 2)                 // 40,960 B

__global__ __launch_bounds__(256, 2) void proj_mma_kernel(
    const float* __restrict__ bq_in, const float* __restrict__ bk_in)
{
    const int z = blockIdx.z;
    const __half* __restrict__ X = z ? g_hKin : g_hQin;
    const __half* __restrict__ W = z ? g_hWk : g_hWq;
    const float* __restrict__ bias = z ? bk_in : bq_in;
    const float scale = z ? 1.0f : QSCALE;
    __half* __restrict__ Out = z ? g_K : g_Q;

    extern __shared__ __half pjs[];
    __half* Xs = pjs;                  // [2][128][40]
    __half* Ws = pjs + 2 * PJ_BUF;     // [2][128][40]
    const uint32_t sb_x = smem_u32(Xs);
    const uint32_t sb_w = smem_u32(Ws);

    const int tid = threadIdx.x;
    const int lane = tid & 31, wid = tid >> 5;
    const int lq = lane & 3, lg = lane >> 2;
    const int n0 = blockIdx.x * 128, m0 = blockIdx.y * 128;
    const int row_lo = wid * 16 + lg;

    // ldmatrix lane offsets (bytes)
    const uint32_t lofA = (uint32_t)(((wid * 16 + (lane & 7) + ((lane >> 3) & 1) * 8) * PJ_H
                                      + ((lane >> 4) & 1) * 8) * 2);
    const uint32_t lofB = (uint32_t)((((lane & 7) + ((lane >> 4) & 1) * 8) * PJ_H
                                      + ((lane >> 3) & 1) * 8) * 2);

    auto prefetch = [&](int st, int kb) {
        if (tid < 128) {
            uint32_t xs = sb_x + (uint32_t)((st * PJ_BUF + tid * PJ_H) * 2);
            const __half* xg = X + (size_t)(m0 + tid) * ND + kb;
#pragma unroll
            for (int i = 0; i < 4; i++) cp16(xs + i * 16, xg + i * 8);
        } else {
            int r = tid - 128;
            uint32_t ws = sb_w + (uint32_t)((st * PJ_BUF + r * PJ_H) * 2);
            const __half* wg = W + (size_t)(n0 + r) * ND + kb;
#pragma unroll
            for (int i = 0; i < 4; i++) cp16(ws + i * 16, wg + i * 8);
        }
    };

    float acc[16][4];
#pragma unroll
    for (int nt = 0; nt < 16; nt++)
#pragma unroll
        for (int j = 0; j < 4; j++) acc[nt][j] = 0.0f;

    prefetch(0, 0);
    CP_COMMIT();

    for (int kb_i = 0; kb_i < ND / 32; kb_i++) {
        if (kb_i + 1 < ND / 32) prefetch((kb_i + 1) & 1, (kb_i + 1) * 32);
        CP_COMMIT();
        CP_WAIT1();
        __syncthreads();

        const uint32_t xb = sb_x + (uint32_t)((kb_i & 1) * PJ_BUF * 2) + lofA;
        const uint32_t wb = sb_w + (uint32_t)((kb_i & 1) * PJ_BUF * 2) + lofB;
#pragma unroll
        for (int s = 0; s < 2; s++) {
            uint32_t a[4];
            LDSM_X4(a, xb + s * 32);
#pragma unroll
            for (int ntp = 0; ntp < 8; ntp++) {
                uint32_t b[4];
                LDSM_X4(b, wb + ntp * (16 * PJ_H * 2) + s * 32);
                MMA_F16(acc[2 * ntp], a, b[0], b[1]);
                MMA_F16(acc[2 * ntp + 1], a, b[2], b[3]);
            }
        }
        __syncthreads();
    }

    // Epilogue: bias + scale, convert fp16, scatter to [bh, s, hd]
    const int m_lo = m0 + row_lo;
    const int b_lo = m_lo >> 11, s_lo = m_lo & 2047;
    const int m_hi = m_lo + 8;
    const int b_hi = m_hi >> 11, s_hi = m_hi & 2047;
#pragma unroll
    for (int nt = 0; nt < 16; nt++) {
        int n = n0 + nt * 8 + 2 * lq;
        float2 bb = *(const float2*)&bias[n];
        int h = n >> 6, hd = n & 63;
        __half2 o0 = __floats2half2_rn((acc[nt][0] + bb.x) * scale,
                                       (acc[nt][1] + bb.y) * scale);
        __half2 o1 = __floats2half2_rn((acc[nt][2] + bb.x) * scale,
                                       (acc[nt][3] + bb.y) * scale);
        *(__half2*)&Out[((size_t)(b_lo * NH + h) * NS + s_lo) * NHD + hd] = o0;
        *(__half2*)&Out[((size_t)(b_hi * NH + h) * NS + s_hi) * NHD + hd] = o1;
    }
}

// ---------------------------------------------------------------------------
// Score kernel (fp16 mma + ldmatrix/stmatrix, double-buffered K):
//   CTA = (head bh, q-tile 128). 16 key tiles of 128. 8 warps, warp = 16x128.
// SMEM: Qs[128][72]h | Ks[2][128][72]h | stg[8][16][136]h   = 90,112 B
// ---------------------------------------------------------------------------
#define QS_H 72
#define KS_OFF  (128 * QS_H * 2)                       // 18,432 B
#define STG_OFF (KS_OFF + 2 * 128 * QS_H * 2)          // 55,296 B
#define STG_ROW 136
#define SC_SMEM_TOTAL (STG_OFF + 8 * 16 * STG_ROW * 2) // 90,112 B

__global__ __launch_bounds__(256, 2) void score_kernel()
{
    extern __shared__ char smem[];
    __half* Qs = (__half*)smem;                     // [128][72]
    __half* Ks = (__half*)(smem + KS_OFF);          // [2][128][72]
    __half* stgall = (__half*)(smem + STG_OFF);
    const uint32_t sb_q = smem_u32(Qs);
    const uint32_t sb_k = smem_u32(Ks);

    const int tid = threadIdx.x;
    const int lane = tid & 31;
    const int wid = tid >> 5;
    const int lq = lane & 3;
    const int lg = lane >> 2;
    const int bh = blockIdx.x;
    const int q0 = blockIdx.y * 128;

    __half* stg = stgall + wid * 16 * STG_ROW;

    // ldmatrix / stmatrix lane offsets (bytes)
    const uint32_t lofA = (uint32_t)(((wid * 16 + (lane & 7) + ((lane >> 3) & 1) * 8) * QS_H
                                      + ((lane >> 4) & 1) * 8) * 2);
    const uint32_t lofB = (uint32_t)((((lane & 7) + ((lane >> 4) & 1) * 8) * QS_H
                                      + ((lane >> 3) & 1) * 8) * 2);
    const uint32_t sb_stg = smem_u32(stg)
        + (uint32_t)((((lane & 7) + ((lane >> 4) & 1) * 8) * STG_ROW
                      + ((lane >> 3) & 1) * 8) * 2);

    const int r_ld = tid >> 1;
    const int c_ld = (tid & 1) * 32;
    auto prefetchK = [&](int st, int kt) {
        uint32_t ks = sb_k + (uint32_t)((st * 128 * QS_H + r_ld * QS_H + c_ld) * 2);
        const __half* kg = g_K + ((size_t)bh * NS + kt * 128 + r_ld) * NHD + c_ld;
#pragma unroll
        for (int i = 0; i < 4; i++) cp16(ks + i * 16, kg + i * 8);
    };

    prefetchK(0, 0);
    CP_COMMIT();
    {
        uint32_t qs = sb_q + (uint32_t)((r_ld * QS_H + c_ld) * 2);
        const __half* qg = g_Q + ((size_t)bh * NS + q0 + r_ld) * NHD + c_ld;
#pragma unroll
        for (int i = 0; i < 4; i++) cp16(qs + i * 16, qg + i * 8);
    }
    CP_COMMIT();
    CP_WAIT0();
    __syncthreads();

    // A fragments via ldmatrix: 4 k16-steps, 16 regs
    const int row_lo = wid * 16 + lg;
    uint32_t afr[4][4];
#pragma unroll
    for (int s = 0; s < 4; s++) LDSM_X4(afr[s], sb_q + lofA + s * 32);

    float rs0 = 0.0f, rs1 = 0.0f;

    for (int kt = 0; kt < NS / 128; kt++) {
        if (kt + 1 < NS / 128) prefetchK((kt + 1) & 1, kt + 1);
        CP_COMMIT();
        CP_WAIT1();
        __syncthreads();

        const uint32_t kb = sb_k + (uint32_t)((kt & 1) * 128 * QS_H * 2) + lofB;

        float acc[16][4];
#pragma unroll
        for (int nt = 0; nt < 16; nt++)
#pragma unroll
            for (int j = 0; j < 4; j++) acc[nt][j] = 0.0f;

#pragma unroll
        for (int s = 0; s < 4; s++) {
#pragma unroll
            for (int ntp = 0; ntp < 8; ntp++) {
                uint32_t b[4];
                LDSM_X4(b, kb + ntp * (16 * QS_H * 2) + s * 32);
                MMA_F16(acc[2 * ntp], afr[s], b[0], b[1]);
                MMA_F16(acc[2 * ntp + 1], afr[s], b[2], b[3]);
            }
        }

        // Epilogue: 2^x -> fp16, stmatrix into staging, coalesced row stores
#pragma unroll
        for (int half = 0; half < 2; half++) {
            uint32_t h2[16];   // [2*nt8 + rowhalf]
#pragma unroll
            for (int nt8 = 0; nt8 < 8; nt8++) {
                const int nt = half * 8 + nt8;
                float e0 = ex2a(acc[nt][0]);
                float e1 = ex2a(acc[nt][1]);
                float e2 = ex2a(acc[nt][2]);
                float e3 = ex2a(acc[nt][3]);
                rs0 += e0 + e1;
                rs1 += e2 + e3;
                __half2 ha = __floats2half2_rn(e0, e1);
                __half2 hb = __floats2half2_rn(e2, e3);
                h2[2 * nt8] = *(uint32_t*)&ha;
                h2[2 * nt8 + 1] = *(uint32_t*)&hb;
            }
#pragma unroll
            for (int ntpl = 0; ntpl < 4; ntpl++) {
                STSM_X4(sb_stg + (half * 4 + ntpl) * 32,
                        h2[4 * ntpl], h2[4 * ntpl + 2],
                        h2[4 * ntpl + 1], h2[4 * ntpl + 3]);
            }
        }
        __syncwarp();
#pragma unroll
        for (int r = 0; r < 16; r++) {
            uint2 v = *(uint2*)&stg[r * STG_ROW + lane * 4];
            *(uint2*)&g_E[((size_t)bh * NS + q0 + wid * 16 + r) * NS + kt * 128 + lane * 4] = v;
        }
        __syncwarp();
        __syncthreads();
    }

    rs0 += __shfl_xor_sync(0xFFFFFFFF, rs0, 1);
    rs0 += __shfl_xor_sync(0xFFFFFFFF, rs0, 2);
    rs1 += __shfl_xor_sync(0xFFFFFFFF, rs1, 1);
    rs1 += __shfl_xor_sync(0xFFFFFFFF, rs1, 2);
    if (lq == 0) {
        g_Linv[bh * NS + q0 + row_lo] = 0.0625f / rs0;
        g_Linv[bh * NS + q0 + row_lo + 8] = 0.0625f / rs1;
    }
}

// ---------------------------------------------------------------------------
// Finalize: out[b,q,k] = sum_h E[b,h,q,k] * Linv[b,h,q]   (pure streaming)
// ---------------------------------------------------------------------------
__global__ __launch_bounds__(256) void finalize_kernel(float* __restrict__ out)
{
    const int tid = threadIdx.x;
    const int bq = blockIdx.x;
    const int b = bq >> 11, q = bq & 2047;

    float acc[8];
#pragma unroll
    for (int j = 0; j < 8; j++) acc[j] = 0.0f;

    for (int h = 0; h < NH; h++) {
        const int bhh = b * NH + h;
        const float w = g_Linv[(bhh << 11) + q];
        const uint4* __restrict__ Ep =
            (const uint4*)(g_E + ((size_t)bhh * NS + q) * NS) + tid;
        uint4 v = *Ep;
        const __half2* hp = (const __half2*)&v;
#pragma unroll
        for (int j = 0; j < 4; j++) {
            float2 f = __half22float2(hp[j]);
            acc[2 * j] += f.x * w;
            acc[2 * j + 1] += f.y * w;
        }
    }

    float4* __restrict__ Op = (float4*)(out + (size_t)bq * NS);
    Op[tid * 2 + 0] = make_float4(acc[0], acc[1], acc[2], acc[3]);
    Op[tid * 2 + 1] = make_float4(acc[4], acc[5], acc[6], acc[7]);
}

// ---------------------------------------------------------------------------
extern "C" void kernel_launch(void* const* d_in, const int* in_sizes, int n_in,
                              void* d_out, int out_size)
{
    const float* query = (const float*)d_in[0];
    const float* key   = (const float*)d_in[1];
    const float* Wq    = (const float*)d_in[2];
    const float* bq    = (const float*)d_in[3];
    const float* Wk    = (const float*)d_in[4];
    const float* bk    = (const float*)d_in[5];
    float* out = (float*)d_out;

    cudaFuncSetAttribute(proj_mma_kernel,
                         cudaFuncAttributeMaxDynamicSharedMemorySize,
                         PJ_SMEM_TOTAL);
    cudaFuncSetAttribute(score_kernel,
                         cudaFuncAttributeMaxDynamicSharedMemorySize,
                         SC_SMEM_TOTAL);

    cvt_kernel<<<CVT_TOTAL / (256 * 8), 256>>>(query, key, Wq, Wk);
    proj_mma_kernel<<<dim3(ND / 128, (NB * NS) / 128, 2), 256, PJ_SMEM_TOTAL>>>(bq, bk);
    score_kernel<<<dim3(NB * NH, NS / 128), 256, SC_SMEM_TOTAL>>>();
    finalize_kernel<<<NB * NS, 256>>>(out);
}

// round 12
// speedup vs baseline: 2.3368x; 1.0057x over previous
#include <cuda_runtime.h>
#include <cuda_fp16.h>
#include <cstdint>

#define NB 2
#define NS 2048
#define ND 1024
#define NH 16
#define NHD 64

// fp16 copies of the inputs (filled by cvt_kernel)
__device__ __half g_hQin[NB * NS * ND];               // 8.4 MB
__device__ __half g_hKin[NB * NS * ND];               // 8.4 MB
__device__ __half g_hWq[ND * ND];                     // 2.1 MB
__device__ __half g_hWk[ND * ND];                     // 2.1 MB

// Scratch — Q/K projections stored as fp16 (Q pre-scaled by 0.125*log2e).
__device__ __half g_Q[NB * NH * NS * NHD];            // 8.4 MB [bh, s, hd]
__device__ __half g_K[NB * NH * NS * NHD];            // 8.4 MB [bh, s, hd]
__device__ __half g_E[(size_t)NB * NH * NS * NS];     // 268 MB fp16 2^scores
__device__ float  g_Linv[NB * NH * NS];               // 1/(16*rowsum)

// ---------------------------------------------------------------------------
__device__ __forceinline__ uint32_t smem_u32(const void* p) {
    uint32_t a;
    asm("{ .reg .u64 t; cvta.to.shared.u64 t, %1; cvt.u32.u64 %0, t; }"
        : "=r"(a) : "l"(p));
    return a;
}
__device__ __forceinline__ void cp16(uint32_t s, const void* g) {
    asm volatile("cp.async.cg.shared.global [%0], [%1], 16;" :: "r"(s), "l"(g));
}
#define CP_COMMIT() asm volatile("cp.async.commit_group;" ::: "memory")
#define CP_WAIT1()  asm volatile("cp.async.wait_group 1;" ::: "memory")
#define CP_WAIT0()  asm volatile("cp.async.wait_group 0;" ::: "memory")

__device__ __forceinline__ float ex2a(float x) {
    float y;
    asm("ex2.approx.f32 %0, %1;" : "=f"(y) : "f"(x));
    return y;
}

// fp16 mma: m16n8k16, fp32 accumulate
#define MMA_F16(d, a, b0, b1)                                                  \
    asm volatile(                                                              \
        "mma.sync.aligned.m16n8k16.row.col.f32.f16.f16.f32 "                   \
        "{%0,%1,%2,%3}, {%4,%5,%6,%7}, {%8,%9}, {%0,%1,%2,%3};"                \
        : "+f"((d)[0]), "+f"((d)[1]), "+f"((d)[2]), "+f"((d)[3])               \
        : "r"((a)[0]), "r"((a)[1]), "r"((a)[2]), "r"((a)[3]),                  \
          "r"(b0), "r"(b1))

#define LDSM_X4(r, addr)                                                       \
    asm volatile("ldmatrix.sync.aligned.m8n8.x4.shared.b16 {%0,%1,%2,%3}, [%4];" \
        : "=r"((r)[0]), "=r"((r)[1]), "=r"((r)[2]), "=r"((r)[3]) : "r"(addr))

#define STSM_X4(addr, r0, r1, r2, r3)                                          \
    asm volatile("stmatrix.sync.aligned.m8n8.x4.shared.b16 [%0], {%1,%2,%3,%4};" \
        :: "r"(addr), "r"(r0), "r"(r1), "r"(r2), "r"(r3) : "memory")

// two fp16 1.0 values — B operand for rowsum-by-mma
#define ONES2 0x3C003C00u

// Q scale folds 1/sqrt(64) and log2(e) so softmax uses raw 2^x.
#define QSCALE 0.18033688011112042f

// ---------------------------------------------------------------------------
// cvt kernel: fp32 inputs -> fp16 buffers. Each thread: 8 elements.
// ---------------------------------------------------------------------------
#define CVT_TOTAL (NB * NS * ND * 2 + ND * ND * 2)     // 10,485,760

__global__ __launch_bounds__(256) void cvt_kernel(
    const float* __restrict__ q, const float* __restrict__ k,
    const float* __restrict__ wq, const float* __restrict__ wk)
{
    const int idx = (blockIdx.x * 256 + threadIdx.x) * 8;
    const float* src;
    __half* dst;
    int off;
    if (idx < NB * NS * ND) {
        src = q; dst = g_hQin; off = idx;
    } else if (idx < 2 * NB * NS * ND) {
        src = k; dst = g_hKin; off = idx - NB * NS * ND;
    } else if (idx < 2 * NB * NS * ND + ND * ND) {
        src = wq; dst = g_hWq; off = idx - 2 * NB * NS * ND;
    } else {
        src = wk; dst = g_hWk; off = idx - 2 * NB * NS * ND - ND * ND;
    }
    float4 f0 = *(const float4*)(src + off);
    float4 f1 = *(const float4*)(src + off + 4);
    uint2 o0, o1;
    *(__half2*)&o0.x = __floats2half2_rn(f0.x, f0.y);
    *(__half2*)&o0.y = __floats2half2_rn(f0.z, f0.w);
    *(__half2*)&o1.x = __floats2half2_rn(f1.x, f1.y);
    *(__half2*)&o1.y = __floats2half2_rn(f1.z, f1.w);
    *(uint4*)(dst + off) = make_uint4(o0.x, o0.y, o1.x, o1.y);
}

// ---------------------------------------------------------------------------
// Projection GEMM (fp16 mma + ldmatrix): Out = (X @ W^T + bias) * scale
//   Fused Q & K via blockIdx.z. BM=128, BN=128, BK=32, double-buffered.
// ---------------------------------------------------------------------------
#define PJ_H 40
#define PJ_BUF (128 * PJ_H)
#define PJ_SMEM_TOTAL (4 * PJ_BUF * 2)                 // 40,960 B

__global__ __launch_bounds__(256, 2) void proj_mma_kernel(
    const float* __restrict__ bq_in, const float* __restrict__ bk_in)
{
    const int z = blockIdx.z;
    const __half* __restrict__ X = z ? g_hKin : g_hQin;
    const __half* __restrict__ W = z ? g_hWk : g_hWq;
    const float* __restrict__ bias = z ? bk_in : bq_in;
    const float scale = z ? 1.0f : QSCALE;
    __half* __restrict__ Out = z ? g_K : g_Q;

    extern __shared__ __half pjs[];
    __half* Xs = pjs;                  // [2][128][40]
    __half* Ws = pjs + 2 * PJ_BUF;     // [2][128][40]
    const uint32_t sb_x = smem_u32(Xs);
    const uint32_t sb_w = smem_u32(Ws);

    const int tid = threadIdx.x;
    const int lane = tid & 31, wid = tid >> 5;
    const int lq = lane & 3, lg = lane >> 2;
    const int n0 = blockIdx.x * 128, m0 = blockIdx.y * 128;
    const int row_lo = wid * 16 + lg;

    const uint32_t lofA = (uint32_t)(((wid * 16 + (lane & 7) + ((lane >> 3) & 1) * 8) * PJ_H
                                      + ((lane >> 4) & 1) * 8) * 2);
    const uint32_t lofB = (uint32_t)((((lane & 7) + ((lane >> 4) & 1) * 8) * PJ_H
                                      + ((lane >> 3) & 1) * 8) * 2);

    auto prefetch = [&](int st, int kb) {
        if (tid < 128) {
            uint32_t xs = sb_x + (uint32_t)((st * PJ_BUF + tid * PJ_H) * 2);
            const __half* xg = X + (size_t)(m0 + tid) * ND + kb;
#pragma unroll
            for (int i = 0; i < 4; i++) cp16(xs + i * 16, xg + i * 8);
        } else {
            int r = tid - 128;
            uint32_t ws = sb_w + (uint32_t)((st * PJ_BUF + r * PJ_H) * 2);
            const __half* wg = W + (size_t)(n0 + r) * ND + kb;
#pragma unroll
            for (int i = 0; i < 4; i++) cp16(ws + i * 16, wg + i * 8);
        }
    };

    float acc[16][4];
#pragma unroll
    for (int nt = 0; nt < 16; nt++)
#pragma unroll
        for (int j = 0; j < 4; j++) acc[nt][j] = 0.0f;

    prefetch(0, 0);
    CP_COMMIT();

    for (int kb_i = 0; kb_i < ND / 32; kb_i++) {
        if (kb_i + 1 < ND / 32) prefetch((kb_i + 1) & 1, (kb_i + 1) * 32);
        CP_COMMIT();
        CP_WAIT1();
        __syncthreads();

        const uint32_t xb = sb_x + (uint32_t)((kb_i & 1) * PJ_BUF * 2) + lofA;
        const uint32_t wb = sb_w + (uint32_t)((kb_i & 1) * PJ_BUF * 2) + lofB;
#pragma unroll
        for (int s = 0; s < 2; s++) {
            uint32_t a[4];
            LDSM_X4(a, xb + s * 32);
#pragma unroll
            for (int ntp = 0; ntp < 8; ntp++) {
                uint32_t b[4];
                LDSM_X4(b, wb + ntp * (16 * PJ_H * 2) + s * 32);
                MMA_F16(acc[2 * ntp], a, b[0], b[1]);
                MMA_F16(acc[2 * ntp + 1], a, b[2], b[3]);
            }
        }
        __syncthreads();
    }

    // Epilogue: bias + scale, convert fp16, scatter to [bh, s, hd]
    const int m_lo = m0 + row_lo;
    const int b_lo = m_lo >> 11, s_lo = m_lo & 2047;
    const int m_hi = m_lo + 8;
    const int b_hi = m_hi >> 11, s_hi = m_hi & 2047;
#pragma unroll
    for (int nt = 0; nt < 16; nt++) {
        int n = n0 + nt * 8 + 2 * lq;
        float2 bb = *(const float2*)&bias[n];
        int h = n >> 6, hd = n & 63;
        __half2 o0 = __floats2half2_rn((acc[nt][0] + bb.x) * scale,
                                       (acc[nt][1] + bb.y) * scale);
        __half2 o1 = __floats2half2_rn((acc[nt][2] + bb.x) * scale,
                                       (acc[nt][3] + bb.y) * scale);
        *(__half2*)&Out[((size_t)(b_lo * NH + h) * NS + s_lo) * NHD + hd] = o0;
        *(__half2*)&Out[((size_t)(b_hi * NH + h) * NS + s_hi) * NHD + hd] = o1;
    }
}

// ---------------------------------------------------------------------------
// Score kernel (fp16 mma + ldmatrix/stmatrix, rowsums via mma-with-ones):
//   CTA = (head bh, q-tile 128). 16 key tiles of 128. 8 warps, warp = 16x128.
// SMEM: Qs[128][72]h | Ks[2][128][72]h | stg[8][16][136]h   = 90,112 B
// ---------------------------------------------------------------------------
#define QS_H 72
#define KS_OFF  (128 * QS_H * 2)                       // 18,432 B
#define STG_OFF (KS_OFF + 2 * 128 * QS_H * 2)          // 55,296 B
#define STG_ROW 136
#define SC_SMEM_TOTAL (STG_OFF + 8 * 16 * STG_ROW * 2) // 90,112 B

__global__ __launch_bounds__(256, 2) void score_kernel()
{
    extern __shared__ char smem[];
    __half* Qs = (__half*)smem;                     // [128][72]
    __half* Ks = (__half*)(smem + KS_OFF);          // [2][128][72]
    __half* stgall = (__half*)(smem + STG_OFF);
    const uint32_t sb_q = smem_u32(Qs);
    const uint32_t sb_k = smem_u32(Ks);

    const int tid = threadIdx.x;
    const int lane = tid & 31;
    const int wid = tid >> 5;
    const int lq = lane & 3;
    const int lg = lane >> 2;
    const int bh = blockIdx.x;
    const int q0 = blockIdx.y * 128;

    __half* stg = stgall + wid * 16 * STG_ROW;

    const uint32_t lofA = (uint32_t)(((wid * 16 + (lane & 7) + ((lane >> 3) & 1) * 8) * QS_H
                                      + ((lane >> 4) & 1) * 8) * 2);
    const uint32_t lofB = (uint32_t)((((lane & 7) + ((lane >> 4) & 1) * 8) * QS_H
                                      + ((lane >> 3) & 1) * 8) * 2);
    const uint32_t sb_stg = smem_u32(stg)
        + (uint32_t)((((lane & 7) + ((lane >> 4) & 1) * 8) * STG_ROW
                      + ((lane >> 3) & 1) * 8) * 2);

    const int r_ld = tid >> 1;
    const int c_ld = (tid & 1) * 32;
    auto prefetchK = [&](int st, int kt) {
        uint32_t ks = sb_k + (uint32_t)((st * 128 * QS_H + r_ld * QS_H + c_ld) * 2);
        const __half* kg = g_K + ((size_t)bh * NS + kt * 128 + r_ld) * NHD + c_ld;
#pragma unroll
        for (int i = 0; i < 4; i++) cp16(ks + i * 16, kg + i * 8);
    };

    prefetchK(0, 0);
    CP_COMMIT();
    {
        uint32_t qs = sb_q + (uint32_t)((r_ld * QS_H + c_ld) * 2);
        const __half* qg = g_Q + ((size_t)bh * NS + q0 + r_ld) * NHD + c_ld;
#pragma unroll
        for (int i = 0; i < 4; i++) cp16(qs + i * 16, qg + i * 8);
    }
    CP_COMMIT();
    CP_WAIT0();
    __syncthreads();

    // A fragments via ldmatrix: 4 k16-steps, 16 regs
    const int row_lo = wid * 16 + lg;
    uint32_t afr[4][4];
#pragma unroll
    for (int s = 0; s < 4; s++) LDSM_X4(afr[s], sb_q + lofA + s * 32);

    // rowsum accumulator (fp32 D-fragment of the rowsum-by-mma); every column
    // of the D tile carries the same value = rowsum.
    float accrs[4] = {0.0f, 0.0f, 0.0f, 0.0f};

    for (int kt = 0; kt < NS / 128; kt++) {
        if (kt + 1 < NS / 128) prefetchK((kt + 1) & 1, kt + 1);
        CP_COMMIT();
        CP_WAIT1();
        __syncthreads();

        const uint32_t kb = sb_k + (uint32_t)((kt & 1) * 128 * QS_H * 2) + lofB;

        float acc[16][4];
#pragma unroll
        for (int nt = 0; nt < 16; nt++)
#pragma unroll
            for (int j = 0; j < 4; j++) acc[nt][j] = 0.0f;

#pragma unroll
        for (int s = 0; s < 4; s++) {
#pragma unroll
            for (int ntp = 0; ntp < 8; ntp++) {
                uint32_t b[4];
                LDSM_X4(b, kb + ntp * (16 * QS_H * 2) + s * 32);
                MMA_F16(acc[2 * ntp], afr[s], b[0], b[1]);
                MMA_F16(acc[2 * ntp + 1], afr[s], b[2], b[3]);
            }
        }

        // Epilogue: 2^x -> fp16; rowsums via mma(E, ones); stmatrix staging.
#pragma unroll
        for (int half = 0; half < 2; half++) {
            uint32_t h2[16];   // [2*nt8 + rowhalf]
#pragma unroll
            for (int nt8 = 0; nt8 < 8; nt8++) {
                const int nt = half * 8 + nt8;
                float e0 = ex2a(acc[nt][0]);
                float e1 = ex2a(acc[nt][1]);
                float e2 = ex2a(acc[nt][2]);
                float e3 = ex2a(acc[nt][3]);
                __half2 ha = __floats2half2_rn(e0, e1);
                __half2 hb = __floats2half2_rn(e2, e3);
                h2[2 * nt8] = *(uint32_t*)&ha;
                h2[2 * nt8 + 1] = *(uint32_t*)&hb;
            }
            // h2[4p..4p+3] is exactly an m16k16 A-fragment of the E tile
            // (cols 16p..16p+15 of this half); multiply by ones -> rowsums.
#pragma unroll
            for (int p = 0; p < 4; p++) {
                uint32_t a[4] = {h2[4 * p], h2[4 * p + 1],
                                 h2[4 * p + 2], h2[4 * p + 3]};
                MMA_F16(accrs, a, ONES2, ONES2);
            }
#pragma unroll
            for (int ntpl = 0; ntpl < 4; ntpl++) {
                STSM_X4(sb_stg + (half * 4 + ntpl) * 32,
                        h2[4 * ntpl], h2[4 * ntpl + 2],
                        h2[4 * ntpl + 1], h2[4 * ntpl + 3]);
            }
        }
        __syncwarp();
        // Vectorized readout: 2 rows per instr (16 lanes x 16B per row)
#pragma unroll
        for (int rr = 0; rr < 8; rr++) {
            int row = rr * 2 + (lane >> 4);
            uint4 v = *(uint4*)&stg[row * STG_ROW + (lane & 15) * 8];
            *(uint4*)&g_E[((size_t)bh * NS + q0 + wid * 16 + row) * NS
                          + kt * 128 + (lane & 15) * 8] = v;
        }
        __syncthreads();   // all warps done with Ks[kt&1] before it is refilled
    }

    // accrs[0] = rowsum(row_lo), accrs[2] = rowsum(row_lo+8); duplicated
    // across the 4 lanes of each quad -> no shuffles needed.
    if (lq == 0) {
        g_Linv[bh * NS + q0 + row_lo] = 0.0625f / accrs[0];
        g_Linv[bh * NS + q0 + row_lo + 8] = 0.0625f / accrs[2];
    }
}

// ---------------------------------------------------------------------------
// Finalize: out[b,q,k] = sum_h E[b,h,q,k] * Linv[b,h,q]   (pure streaming)
// ---------------------------------------------------------------------------
__global__ __launch_bounds__(256) void finalize_kernel(float* __restrict__ out)
{
    const int tid = threadIdx.x;
    const int bq = blockIdx.x;
    const int b = bq >> 11, q = bq & 2047;

    float acc[8];
#pragma unroll
    for (int j = 0; j < 8; j++) acc[j] = 0.0f;

    for (int h = 0; h < NH; h++) {
        const int bhh = b * NH + h;
        const float w = g_Linv[(bhh << 11) + q];
        const uint4* __restrict__ Ep =
            (const uint4*)(g_E + ((size_t)bhh * NS + q) * NS) + tid;
        uint4 v = *Ep;
        const __half2* hp = (const __half2*)&v;
#pragma unroll
        for (int j = 0; j < 4; j++) {
            float2 f = __half22float2(hp[j]);
            acc[2 * j] += f.x * w;
            acc[2 * j + 1] += f.y * w;
        }
    }

    float4* __restrict__ Op = (float4*)(out + (size_t)bq * NS);
    Op[tid * 2 + 0] = make_float4(acc[0], acc[1], acc[2], acc[3]);
    Op[tid * 2 + 1] = make_float4(acc[4], acc[5], acc[6], acc[7]);
}

// ---------------------------------------------------------------------------
extern "C" void kernel_launch(void* const* d_in, const int* in_sizes, int n_in,
                              void* d_out, int out_size)
{
    const float* query = (const float*)d_in[0];
    const float* key   = (const float*)d_in[1];
    const float* Wq    = (const float*)d_in[2];
    const float* bq    = (const float*)d_in[3];
    const float* Wk    = (const float*)d_in[4];
    const float* bk    = (const float*)d_in[5];
    float* out = (float*)d_out;

    cudaFuncSetAttribute(proj_mma_kernel,
                         cudaFuncAttributeMaxDynamicSharedMemorySize,
                         PJ_SMEM_TOTAL);
    cudaFuncSetAttribute(score_kernel,
                         cudaFuncAttributeMaxDynamicSharedMemorySize,
                         SC_SMEM_TOTAL);

    cvt_kernel<<<CVT_TOTAL / (256 * 8), 256>>>(query, key, Wq, Wk);
    proj_mma_kernel<<<dim3(ND / 128, (NB * NS) / 128, 2), 256, PJ_SMEM_TOTAL>>>(bq, bk);
    score_kernel<<<dim3(NB * NH, NS / 128), 256, SC_SMEM_TOTAL>>>();
    finalize_kernel<<<NB * NS, 256>>>(out);
}

// round 13
// speedup vs baseline: 2.4109x; 1.0317x over previous
#include <cuda_runtime.h>
#include <cuda_fp16.h>
#include <cstdint>

#define NB 2
#define NS 2048
#define ND 1024
#define NH 16
#define NHD 64

// fp16 copies of the inputs (filled by cvt_kernel)
__device__ __half g_hQin[NB * NS * ND];
__device__ __half g_hKin[NB * NS * ND];
__device__ __half g_hWq[ND * ND];
__device__ __half g_hWk[ND * ND];

// Scratch — Q/K projections stored as fp16 (Q pre-scaled by 0.125*log2e).
__device__ __half g_Q[NB * NH * NS * NHD];
__device__ __half g_K[NB * NH * NS * NHD];
__device__ __half g_E[(size_t)NB * NH * NS * NS];     // 268 MB fp16 2^scores
__device__ float  g_Linv[NB * NH * NS];               // 1/(16*rowsum)

// ---------------------------------------------------------------------------
__device__ __forceinline__ uint32_t smem_u32(const void* p) {
    uint32_t a;
    asm("{ .reg .u64 t; cvta.to.shared.u64 t, %1; cvt.u32.u64 %0, t; }"
        : "=r"(a) : "l"(p));
    return a;
}
__device__ __forceinline__ void cp16(uint32_t s, const void* g) {
    asm volatile("cp.async.cg.shared.global [%0], [%1], 16;" :: "r"(s), "l"(g));
}
#define CP_COMMIT() asm volatile("cp.async.commit_group;" ::: "memory")
#define CP_WAIT1()  asm volatile("cp.async.wait_group 1;" ::: "memory")
#define CP_WAIT0()  asm volatile("cp.async.wait_group 0;" ::: "memory")

__device__ __forceinline__ float ex2a(float x) {
    float y;
    asm("ex2.approx.f32 %0, %1;" : "=f"(y) : "f"(x));
    return y;
}

#define MMA_F16(d, a, b0, b1)                                                  \
    asm volatile(                                                              \
        "mma.sync.aligned.m16n8k16.row.col.f32.f16.f16.f32 "                   \
        "{%0,%1,%2,%3}, {%4,%5,%6,%7}, {%8,%9}, {%0,%1,%2,%3};"                \
        : "+f"((d)[0]), "+f"((d)[1]), "+f"((d)[2]), "+f"((d)[3])               \
        : "r"((a)[0]), "r"((a)[1]), "r"((a)[2]), "r"((a)[3]),                  \
          "r"(b0), "r"(b1))

#define LDSM_X4(r, addr)                                                       \
    asm volatile("ldmatrix.sync.aligned.m8n8.x4.shared.b16 {%0,%1,%2,%3}, [%4];" \
        : "=r"((r)[0]), "=r"((r)[1]), "=r"((r)[2]), "=r"((r)[3]) : "r"(addr))

#define STSM_X4(addr, r0, r1, r2, r3)                                          \
    asm volatile("stmatrix.sync.aligned.m8n8.x4.shared.b16 [%0], {%1,%2,%3,%4};" \
        :: "r"(addr), "r"(r0), "r"(r1), "r"(r2), "r"(r3) : "memory")

#define ONES2 0x3C003C00u
#define QSCALE 0.18033688011112042f

// ---------------------------------------------------------------------------
// cvt kernel: fp32 inputs -> fp16 buffers.
// ---------------------------------------------------------------------------
#define CVT_TOTAL (NB * NS * ND * 2 + ND * ND * 2)

__global__ __launch_bounds__(256) void cvt_kernel(
    const float* __restrict__ q, const float* __restrict__ k,
    const float* __restrict__ wq, const float* __restrict__ wk)
{
    const int idx = (blockIdx.x * 256 + threadIdx.x) * 8;
    const float* src;
    __half* dst;
    int off;
    if (idx < NB * NS * ND) {
        src = q; dst = g_hQin; off = idx;
    } else if (idx < 2 * NB * NS * ND) {
        src = k; dst = g_hKin; off = idx - NB * NS * ND;
    } else if (idx < 2 * NB * NS * ND + ND * ND) {
        src = wq; dst = g_hWq; off = idx - 2 * NB * NS * ND;
    } else {
        src = wk; dst = g_hWk; off = idx - 2 * NB * NS * ND - ND * ND;
    }
    float4 f0 = *(const float4*)(src + off);
    float4 f1 = *(const float4*)(src + off + 4);
    uint2 o0, o1;
    *(__half2*)&o0.x = __floats2half2_rn(f0.x, f0.y);
    *(__half2*)&o0.y = __floats2half2_rn(f0.z, f0.w);
    *(__half2*)&o1.x = __floats2half2_rn(f1.x, f1.y);
    *(__half2*)&o1.y = __floats2half2_rn(f1.z, f1.w);
    *(uint4*)(dst + off) = make_uint4(o0.x, o0.y, o1.x, o1.y);
}

// ---------------------------------------------------------------------------
// Projection GEMM (fp16 mma + ldmatrix, 4x2 warp layout):
//   warp = 32 m-rows x 64 n-cols. Per iter: 4 A-LDSM + 8 B-LDSM + 32 HMMA.
// ---------------------------------------------------------------------------
#define PJ_H 40
#define PJ_BUF (128 * PJ_H)
#define PJ_SMEM_TOTAL (4 * PJ_BUF * 2)                 // 40,960 B

__global__ __launch_bounds__(256, 2) void proj_mma_kernel(
    const float* __restrict__ bq_in, const float* __restrict__ bk_in)
{
    const int z = blockIdx.z;
    const __half* __restrict__ X = z ? g_hKin : g_hQin;
    const __half* __restrict__ W = z ? g_hWk : g_hWq;
    const float* __restrict__ bias = z ? bk_in : bq_in;
    const float scale = z ? 1.0f : QSCALE;
    __half* __restrict__ Out = z ? g_K : g_Q;

    extern __shared__ __half pjs[];
    __half* Xs = pjs;                  // [2][128][40]
    __half* Ws = pjs + 2 * PJ_BUF;     // [2][128][40]
    const uint32_t sb_x = smem_u32(Xs);
    const uint32_t sb_w = smem_u32(Ws);

    const int tid = threadIdx.x;
    const int lane = tid & 31, wid = tid >> 5;
    const int lq = lane & 3, lg = lane >> 2;
    const int wm = wid >> 1, wn = wid & 1;
    const int n0 = blockIdx.x * 128, m0 = blockIdx.y * 128;

    // ldmatrix lane offsets (bytes)
    const int lrow = (lane & 7) + ((lane >> 3) & 1) * 8;   // A row-in-16 / B n-in-16
    const int lrowB = (lane & 7) + ((lane >> 4) & 1) * 8;
    const uint32_t lofA0 = (uint32_t)(((wm * 32 + lrow) * PJ_H + ((lane >> 4) & 1) * 8) * 2);
    const uint32_t lofA1 = (uint32_t)(((wm * 32 + 16 + lrow) * PJ_H + ((lane >> 4) & 1) * 8) * 2);
    const uint32_t lofB = (uint32_t)(((wn * 64 + lrowB) * PJ_H + ((lane >> 3) & 1) * 8) * 2);

    auto prefetch = [&](int st, int kb) {
        if (tid < 128) {
            uint32_t xs = sb_x + (uint32_t)((st * PJ_BUF + tid * PJ_H) * 2);
            const __half* xg = X + (size_t)(m0 + tid) * ND + kb;
#pragma unroll
            for (int i = 0; i < 4; i++) cp16(xs + i * 16, xg + i * 8);
        } else {
            int r = tid - 128;
            uint32_t ws = sb_w + (uint32_t)((st * PJ_BUF + r * PJ_H) * 2);
            const __half* wg = W + (size_t)(n0 + r) * ND + kb;
#pragma unroll
            for (int i = 0; i < 4; i++) cp16(ws + i * 16, wg + i * 8);
        }
    };

    float acc[2][8][4];
#pragma unroll
    for (int mt = 0; mt < 2; mt++)
#pragma unroll
        for (int nt = 0; nt < 8; nt++)
#pragma unroll
            for (int j = 0; j < 4; j++) acc[mt][nt][j] = 0.0f;

    prefetch(0, 0);
    CP_COMMIT();

    for (int kb_i = 0; kb_i < ND / 32; kb_i++) {
        if (kb_i + 1 < ND / 32) prefetch((kb_i + 1) & 1, (kb_i + 1) * 32);
        CP_COMMIT();
        CP_WAIT1();
        __syncthreads();

        const uint32_t xb = sb_x + (uint32_t)((kb_i & 1) * PJ_BUF * 2);
        const uint32_t wb = sb_w + (uint32_t)((kb_i & 1) * PJ_BUF * 2) + lofB;
#pragma unroll
        for (int s = 0; s < 2; s++) {
            uint32_t a0[4], a1[4];
            LDSM_X4(a0, xb + lofA0 + s * 32);
            LDSM_X4(a1, xb + lofA1 + s * 32);
#pragma unroll
            for (int ntp = 0; ntp < 4; ntp++) {
                uint32_t b[4];
                LDSM_X4(b, wb + ntp * (16 * PJ_H * 2) + s * 32);
                MMA_F16(acc[0][2 * ntp], a0, b[0], b[1]);
                MMA_F16(acc[0][2 * ntp + 1], a0, b[2], b[3]);
                MMA_F16(acc[1][2 * ntp], a1, b[0], b[1]);
                MMA_F16(acc[1][2 * ntp + 1], a1, b[2], b[3]);
            }
        }
        __syncthreads();
    }

    // Epilogue: bias + scale, convert fp16, scatter to [bh, s, hd]
#pragma unroll
    for (int mt = 0; mt < 2; mt++) {
        const int m_lo = m0 + wm * 32 + mt * 16 + lg;
        const int b_lo = m_lo >> 11, s_lo = m_lo & 2047;
        const int m_hi = m_lo + 8;
        const int b_hi = m_hi >> 11, s_hi = m_hi & 2047;
#pragma unroll
        for (int nt = 0; nt < 8; nt++) {
            int n = n0 + wn * 64 + nt * 8 + 2 * lq;
            float2 bb = *(const float2*)&bias[n];
            int h = n >> 6, hd = n & 63;
            __half2 o0 = __floats2half2_rn((acc[mt][nt][0] + bb.x) * scale,
                                           (acc[mt][nt][1] + bb.y) * scale);
            __half2 o1 = __floats2half2_rn((acc[mt][nt][2] + bb.x) * scale,
                                           (acc[mt][nt][3] + bb.y) * scale);
            *(__half2*)&Out[((size_t)(b_lo * NH + h) * NS + s_lo) * NHD + hd] = o0;
            *(__half2*)&Out[((size_t)(b_hi * NH + h) * NS + s_hi) * NHD + hd] = o1;
        }
    }
}

// ---------------------------------------------------------------------------
// Score kernel (fp16 mma, 4x2 warp layout: warp = 32 q-rows x 64 k-cols):
//   CTA = (head bh, q-tile 128). 16 key tiles of 128. 8 warps.
//   Per warp per tile: 16 B-LDSM + 64 HMMA + 8 rowsum-HMMA.
// SMEM: Qs[128][72]h | Ks[2][128][72]h | stg[8][32][72]h   = 92,160 B
// ---------------------------------------------------------------------------
#define QS_H 72
#define KS_OFF  (128 * QS_H * 2)                       // 18,432 B
#define STG_OFF (KS_OFF + 2 * 128 * QS_H * 2)          // 55,296 B
#define ST2 72
#define SC_SMEM_TOTAL (STG_OFF + 8 * 32 * ST2 * 2)     // 92,160 B

__global__ __launch_bounds__(256, 2) void score_kernel()
{
    extern __shared__ char smem[];
    __half* Qs = (__half*)smem;                     // [128][72]
    __half* Ks = (__half*)(smem + KS_OFF);          // [2][128][72]
    __half* stgall = (__half*)(smem + STG_OFF);     // [8][32][72]
    const uint32_t sb_q = smem_u32(Qs);
    const uint32_t sb_k = smem_u32(Ks);

    const int tid = threadIdx.x;
    const int lane = tid & 31;
    const int wid = tid >> 5;
    const int lq = lane & 3;
    const int lg = lane >> 2;
    const int wm = wid >> 1, wn = wid & 1;
    const int bh = blockIdx.x;
    const int q0 = blockIdx.y * 128;

    __half* stgw = stgall + wid * 32 * ST2;

    const int lrowA = (lane & 7) + ((lane >> 3) & 1) * 8;
    const int lrowB = (lane & 7) + ((lane >> 4) & 1) * 8;
    const uint32_t lofA0 = (uint32_t)(((wm * 32 + lrowA) * QS_H + ((lane >> 4) & 1) * 8) * 2);
    const uint32_t lofA1 = (uint32_t)(((wm * 32 + 16 + lrowA) * QS_H + ((lane >> 4) & 1) * 8) * 2);
    const uint32_t lofB = (uint32_t)(((wn * 64 + lrowB) * QS_H + ((lane >> 3) & 1) * 8) * 2);
    // stmatrix staging lane offset: row = (lane&7) + ((lane>>4)&1)*8, col-half = ((lane>>3)&1)*8
    const uint32_t sb_stg = smem_u32(stgw)
        + (uint32_t)((((lane & 7) + ((lane >> 4) & 1) * 8) * ST2
                      + ((lane >> 3) & 1) * 8) * 2);

    const int r_ld = tid >> 1;
    const int c_ld = (tid & 1) * 32;
    auto prefetchK = [&](int st, int kt) {
        uint32_t ks = sb_k + (uint32_t)((st * 128 * QS_H + r_ld * QS_H + c_ld) * 2);
        const __half* kg = g_K + ((size_t)bh * NS + kt * 128 + r_ld) * NHD + c_ld;
#pragma unroll
        for (int i = 0; i < 4; i++) cp16(ks + i * 16, kg + i * 8);
    };

    prefetchK(0, 0);
    CP_COMMIT();
    {
        uint32_t qs = sb_q + (uint32_t)((r_ld * QS_H + c_ld) * 2);
        const __half* qg = g_Q + ((size_t)bh * NS + q0 + r_ld) * NHD + c_ld;
#pragma unroll
        for (int i = 0; i < 4; i++) cp16(qs + i * 16, qg + i * 8);
    }
    CP_COMMIT();
    CP_WAIT0();
    __syncthreads();

    // A fragments: 4 k16-steps x 2 m16-tiles; 32 regs
    uint32_t afr[4][2][4];
#pragma unroll
    for (int s = 0; s < 4; s++) {
        LDSM_X4(afr[s][0], sb_q + lofA0 + s * 32);
        LDSM_X4(afr[s][1], sb_q + lofA1 + s * 32);
    }

    // rowsum accumulators (partial over this warp's 64 cols)
    float accrs[2][4];
#pragma unroll
    for (int mt = 0; mt < 2; mt++)
#pragma unroll
        for (int j = 0; j < 4; j++) accrs[mt][j] = 0.0f;

    for (int kt = 0; kt < NS / 128; kt++) {
        if (kt + 1 < NS / 128) prefetchK((kt + 1) & 1, kt + 1);
        CP_COMMIT();
        CP_WAIT1();
        __syncthreads();

        const uint32_t kb = sb_k + (uint32_t)((kt & 1) * 128 * QS_H * 2) + lofB;

        float acc[2][8][4];
#pragma unroll
        for (int mt = 0; mt < 2; mt++)
#pragma unroll
            for (int nt = 0; nt < 8; nt++)
#pragma unroll
                for (int j = 0; j < 4; j++) acc[mt][nt][j] = 0.0f;

#pragma unroll
        for (int s = 0; s < 4; s++) {
#pragma unroll
            for (int ntp = 0; ntp < 4; ntp++) {
                uint32_t b[4];
                LDSM_X4(b, kb + ntp * (16 * QS_H * 2) + s * 32);
                MMA_F16(acc[0][2 * ntp], afr[s][0], b[0], b[1]);
                MMA_F16(acc[0][2 * ntp + 1], afr[s][0], b[2], b[3]);
                MMA_F16(acc[1][2 * ntp], afr[s][1], b[0], b[1]);
                MMA_F16(acc[1][2 * ntp + 1], afr[s][1], b[2], b[3]);
            }
        }

        // Epilogue: 2^x -> fp16; rowsums via mma(E, ones); stmatrix staging.
#pragma unroll
        for (int mt = 0; mt < 2; mt++) {
            uint32_t h2[16];
#pragma unroll
            for (int nt = 0; nt < 8; nt++) {
                float e0 = ex2a(acc[mt][nt][0]);
                float e1 = ex2a(acc[mt][nt][1]);
                float e2 = ex2a(acc[mt][nt][2]);
                float e3 = ex2a(acc[mt][nt][3]);
                __half2 ha = __floats2half2_rn(e0, e1);
                __half2 hb = __floats2half2_rn(e2, e3);
                h2[2 * nt] = *(uint32_t*)&ha;
                h2[2 * nt + 1] = *(uint32_t*)&hb;
            }
#pragma unroll
            for (int p = 0; p < 4; p++) {
                uint32_t a[4] = {h2[4 * p], h2[4 * p + 1],
                                 h2[4 * p + 2], h2[4 * p + 3]};
                MMA_F16(accrs[mt], a, ONES2, ONES2);
            }
#pragma unroll
            for (int p = 0; p < 4; p++) {
                STSM_X4(sb_stg + (uint32_t)(mt * 16 * ST2 * 2) + p * 32,
                        h2[4 * p], h2[4 * p + 2],
                        h2[4 * p + 1], h2[4 * p + 3]);
            }
        }
        __syncwarp();
        // Readout: warp region 32 rows x 128 B; 4 rows per uint4 instr
#pragma unroll
        for (int rr = 0; rr < 8; rr++) {
            int row = rr * 4 + (lane >> 3);
            uint4 v = *(uint4*)&stgw[row * ST2 + (lane & 7) * 8];
            *(uint4*)&g_E[((size_t)bh * NS + q0 + wm * 32 + row) * NS
                          + kt * 128 + wn * 64 + (lane & 7) * 8] = v;
        }
        __syncthreads();
    }

    // Combine the two wn-partials per row; write Linv (with /16 folded).
    float* rsb = (float*)stgall;          // 256 floats; stg is dead now
    if (lq == 0) {
#pragma unroll
        for (int mt = 0; mt < 2; mt++) {
            int r = wm * 32 + mt * 16 + lg;
            rsb[wn * 128 + r] = accrs[mt][0];
            rsb[wn * 128 + r + 8] = accrs[mt][2];
        }
    }
    __syncthreads();
    if (tid < 128) {
        g_Linv[bh * NS + q0 + tid] = 0.0625f / (rsb[tid] + rsb[128 + tid]);
    }
}

// ---------------------------------------------------------------------------
// Finalize: out[b,q,k] = sum_h E[b,h,q,k] * Linv[b,h,q]   (pure streaming)
// ---------------------------------------------------------------------------
__global__ __launch_bounds__(256) void finalize_kernel(float* __restrict__ out)
{
    const int tid = threadIdx.x;
    const int bq = blockIdx.x;
    const int b = bq >> 11, q = bq & 2047;

    float acc[8];
#pragma unroll
    for (int j = 0; j < 8; j++) acc[j] = 0.0f;

    for (int h = 0; h < NH; h++) {
        const int bhh = b * NH + h;
        const float w = g_Linv[(bhh << 11) + q];
        const uint4* __restrict__ Ep =
            (const uint4*)(g_E + ((size_t)bhh * NS + q) * NS) + tid;
        uint4 v = *Ep;
        const __half2* hp = (const __half2*)&v;
#pragma unroll
        for (int j = 0; j < 4; j++) {
            float2 f = __half22float2(hp[j]);
            acc[2 * j] += f.x * w;
            acc[2 * j + 1] += f.y * w;
        }
    }

    float4* __restrict__ Op = (float4*)(out + (size_t)bq * NS);
    Op[tid * 2 + 0] = make_float4(acc[0], acc[1], acc[2], acc[3]);
    Op[tid * 2 + 1] = make_float4(acc[4], acc[5], acc[6], acc[7]);
}

// ---------------------------------------------------------------------------
extern "C" void kernel_launch(void* const* d_in, const int* in_sizes, int n_in,
                              void* d_out, int out_size)
{
    const float* query = (const float*)d_in[0];
    const float* key   = (const float*)d_in[1];
    const float* Wq    = (const float*)d_in[2];
    const float* bq    = (const float*)d_in[3];
    const float* Wk    = (const float*)d_in[4];
    const float* bk    = (const float*)d_in[5];
    float* out = (float*)d_out;

    cudaFuncSetAttribute(proj_mma_kernel,
                         cudaFuncAttributeMaxDynamicSharedMemorySize,
                         PJ_SMEM_TOTAL);
    cudaFuncSetAttribute(score_kernel,
                         cudaFuncAttributeMaxDynamicSharedMemorySize,
                         SC_SMEM_TOTAL);

    cvt_kernel<<<CVT_TOTAL / (256 * 8), 256>>>(query, key, Wq, Wk);
    proj_mma_kernel<<<dim3(ND / 128, (NB * NS) / 128, 2), 256, PJ_SMEM_TOTAL>>>(bq, bk);
    score_kernel<<<dim3(NB * NH, NS / 128), 256, SC_SMEM_TOTAL>>>();
    finalize_kernel<<<NB * NS, 256>>>(out);
}